// round 1
// baseline (speedup 1.0000x reference)
#include <cuda_runtime.h>
#include <math.h>

#define BB 4
#define SS 2048
#define DD 1024
#define NH 16
#define DKH 64
#define MM (BB*SS)      // 8192 rows
#define WND 256
#define GLB 16

// Scratch (allocation-free rule: __device__ globals)
__device__ float g_Q[MM*DD];
__device__ float g_K[MM*DD];
__device__ float g_V[MM*DD];
__device__ float g_AO[MM*DD];

// ---------------------------------------------------------------------------
// fp32 SGEMM with bias: C[M,N] = A[M,K] @ B[K,N] + bias[N]
// 128x128 block tile, K-step 8, 256 threads, 8x8 per-thread microtile.
// ---------------------------------------------------------------------------
__global__ __launch_bounds__(256, 2)
void sgemm_bias(const float* __restrict__ A, const float* __restrict__ Bw,
                const float* __restrict__ bias, float* __restrict__ C,
                int M, int N, int K)
{
    __shared__ float As[8][132];   // transposed A tile, padded (conflict-free)
    __shared__ float Bs[8][128];

    const int tid = threadIdx.x;
    const int tx = tid & 15, ty = tid >> 4;
    const int m0 = blockIdx.y * 128, n0 = blockIdx.x * 128;

    const int a_row = tid >> 1;          // 0..127
    const int a_col = (tid & 1) * 4;     // 0 or 4
    const int b_row = tid >> 5;          // 0..7
    const int b_col = (tid & 31) * 4;    // 0..124

    const float* Ap = A + (long)(m0 + a_row) * K + a_col;
    const float* Bp = Bw + (long)b_row * N + n0 + b_col;

    float acc[8][8];
#pragma unroll
    for (int i = 0; i < 8; i++)
#pragma unroll
        for (int j = 0; j < 8; j++) acc[i][j] = 0.f;

    float4 av = *(const float4*)Ap;
    float4 bv = *(const float4*)Bp;

    for (int k0 = 0; k0 < K; k0 += 8) {
        As[a_col + 0][a_row] = av.x;
        As[a_col + 1][a_row] = av.y;
        As[a_col + 2][a_row] = av.z;
        As[a_col + 3][a_row] = av.w;
        *(float4*)&Bs[b_row][b_col] = bv;
        __syncthreads();

        if (k0 + 8 < K) {   // prefetch next slab into registers
            av = *(const float4*)(Ap + k0 + 8);
            bv = *(const float4*)(Bp + (long)(k0 + 8) * N);
        }

#pragma unroll
        for (int k = 0; k < 8; k++) {
            float a[8], b[8];
            *(float4*)&a[0] = *(const float4*)&As[k][ty * 8];
            *(float4*)&a[4] = *(const float4*)&As[k][ty * 8 + 4];
            *(float4*)&b[0] = *(const float4*)&Bs[k][tx * 8];
            *(float4*)&b[4] = *(const float4*)&Bs[k][tx * 8 + 4];
#pragma unroll
            for (int i = 0; i < 8; i++)
#pragma unroll
                for (int j = 0; j < 8; j++)
                    acc[i][j] = fmaf(a[i], b[j], acc[i][j]);
        }
        __syncthreads();
    }

#pragma unroll
    for (int i = 0; i < 8; i++) {
        long m = m0 + ty * 8 + i;
#pragma unroll
        for (int j = 0; j < 8; j += 4) {
            int n = n0 + tx * 8 + j;
            float4 o;
            o.x = acc[i][j + 0] + bias[n + 0];
            o.y = acc[i][j + 1] + bias[n + 1];
            o.z = acc[i][j + 2] + bias[n + 2];
            o.w = acc[i][j + 3] + bias[n + 3];
            *(float4*)&C[m * N + n] = o;
        }
    }
}

// ---------------------------------------------------------------------------
// Sparse flash attention (local window + global tokens), fp32.
// Grid: (32 q-tiles, 16 heads, 4 batch). 256 threads. 64q x 64k tiles.
// ---------------------------------------------------------------------------
__global__ __launch_bounds__(256)
void attn_kernel(const float* __restrict__ Q, const float* __restrict__ K,
                 const float* __restrict__ V, const float* __restrict__ amask,
                 float* __restrict__ O)
{
    extern __shared__ float sm[];
    float* Qs   = sm;                 // 64 x 68 (padded, pre-scaled)
    float* Ks   = Qs + 64 * 68;       // 64 x 68
    float* Vs   = Ks + 64 * 68;       // 64 x 64
    float* Ssm  = Vs + 64 * 64;       // 64 x 65 (scores -> probs)
    float* rowm = Ssm + 64 * 65;      // 64 running max
    float* rowl = rowm + 64;          // 64 running sum
    float* rowsc = rowl + 64;         // 64 rescale factors

    const int tid = threadIdx.x;
    const int qt = blockIdx.x, h = blockIdx.y, b = blockIdx.z;
    const int q0 = qt * 64;
    const long baserow = (long)b * SS;
    const int hc = h * DKH;

    // Load + pre-scale Q tile (scale = 1/sqrt(64) = 0.125)
    for (int idx = tid; idx < 64 * 16; idx += 256) {
        int qi = idx >> 4, kk = idx & 15;
        float4 v4 = *(const float4*)&Q[(baserow + q0 + qi) * DD + hc + kk * 4];
        v4.x *= 0.125f; v4.y *= 0.125f; v4.z *= 0.125f; v4.w *= 0.125f;
        *(float4*)&Qs[qi * 68 + kk * 4] = v4;
    }
    if (tid < 64) { rowm[tid] = -INFINITY; rowl[tid] = 0.f; }

    float Oacc[16];
#pragma unroll
    for (int u = 0; u < 16; u++) Oacc[u] = 0.f;

    const int qg  = tid >> 4;   // 0..15 : query group (4 rows)
    const int jg  = tid & 15;   // 0..15 : key group (4 cols)
    const int oqi = tid >> 2;   // 0..63 : output row
    const int oc  = tid & 3;    // 0..3  : output dk block (16 wide)

    const int jt_lo = max(0, (q0 - WND) >> 6);
    const int jt_hi = min(31, (q0 + 63 + WND) >> 6);

    __syncthreads();

    for (int jt = 0; jt < 32; jt++) {
        // qt==0 contains global queries -> scan everything; others: window + tile 0
        bool active = (qt == 0) || (jt == 0) || (jt >= jt_lo && jt <= jt_hi);
        if (!active) continue;
        const int j0 = jt * 64;

        // Load K, V tiles
        for (int idx = tid; idx < 64 * 16; idx += 256) {
            int ji = idx >> 4, kk = idx & 15;
            *(float4*)&Ks[ji * 68 + kk * 4] =
                *(const float4*)&K[(baserow + j0 + ji) * DD + hc + kk * 4];
            *(float4*)&Vs[ji * 64 + kk * 4] =
                *(const float4*)&V[(baserow + j0 + ji) * DD + hc + kk * 4];
        }
        __syncthreads();

        // Scores: each thread computes a 4x4 microtile
        float accS[4][4];
#pragma unroll
        for (int a = 0; a < 4; a++)
#pragma unroll
            for (int c = 0; c < 4; c++) accS[a][c] = 0.f;

#pragma unroll 4
        for (int kk = 0; kk < 16; kk++) {
            float4 qv[4], kv[4];
#pragma unroll
            for (int a = 0; a < 4; a++)
                qv[a] = *(const float4*)&Qs[(qg * 4 + a) * 68 + kk * 4];
#pragma unroll
            for (int c = 0; c < 4; c++)
                kv[c] = *(const float4*)&Ks[(jg * 4 + c) * 68 + kk * 4];
#pragma unroll
            for (int a = 0; a < 4; a++)
#pragma unroll
                for (int c = 0; c < 4; c++) {
                    accS[a][c] = fmaf(qv[a].x, kv[c].x, accS[a][c]);
                    accS[a][c] = fmaf(qv[a].y, kv[c].y, accS[a][c]);
                    accS[a][c] = fmaf(qv[a].z, kv[c].z, accS[a][c]);
                    accS[a][c] = fmaf(qv[a].w, kv[c].w, accS[a][c]);
                }
        }

        // Apply sparsity mask + additive key mask, write to smem
        float mv[4];
#pragma unroll
        for (int c = 0; c < 4; c++)
            mv[c] = amask[b * SS + j0 + jg * 4 + c];
#pragma unroll
        for (int a = 0; a < 4; a++) {
            int i = q0 + qg * 4 + a;
#pragma unroll
            for (int c = 0; c < 4; c++) {
                int j = j0 + jg * 4 + c;
                bool ok = (i < GLB) || (j < GLB) || (abs(i - j) <= WND);
                float s = ok ? (accS[a][c] + mv[c]) : -1e30f;
                Ssm[(qg * 4 + a) * 65 + (jg * 4 + c)] = s;
            }
        }
        __syncthreads();

        // Online-softmax row statistics (one thread per query row)
        if (tid < 64) {
            int r = tid;
            float mold = rowm[r];
            float mmax = mold;
#pragma unroll 8
            for (int j = 0; j < 64; j++) mmax = fmaxf(mmax, Ssm[r * 65 + j]);
            float sc = __expf(mold - mmax);   // 0 on first tile (mold=-inf)
            float lsum = 0.f;
#pragma unroll 8
            for (int j = 0; j < 64; j++) {
                float p = __expf(Ssm[r * 65 + j] - mmax);
                Ssm[r * 65 + j] = p;
                lsum += p;
            }
            rowm[r] = mmax;
            rowl[r] = rowl[r] * sc + lsum;
            rowsc[r] = sc;
        }
        __syncthreads();

        // P @ V accumulate (rescale old accumulator first)
        {
            float sc = rowsc[oqi];
#pragma unroll
            for (int u = 0; u < 16; u++) Oacc[u] *= sc;
#pragma unroll 4
            for (int j = 0; j < 64; j++) {
                float p = Ssm[oqi * 65 + j];
#pragma unroll
                for (int kk = 0; kk < 4; kk++) {
                    float4 vv = *(const float4*)&Vs[j * 64 + oc * 16 + kk * 4];
                    Oacc[kk * 4 + 0] = fmaf(p, vv.x, Oacc[kk * 4 + 0]);
                    Oacc[kk * 4 + 1] = fmaf(p, vv.y, Oacc[kk * 4 + 1]);
                    Oacc[kk * 4 + 2] = fmaf(p, vv.z, Oacc[kk * 4 + 2]);
                    Oacc[kk * 4 + 3] = fmaf(p, vv.w, Oacc[kk * 4 + 3]);
                }
            }
        }
        __syncthreads();
    }

    // Normalize and write out (layout [b*S+s][D], head-major columns)
    float rinv = 1.f / rowl[oqi];
#pragma unroll
    for (int kk = 0; kk < 4; kk++) {
        float4 o;
        o.x = Oacc[kk * 4 + 0] * rinv;
        o.y = Oacc[kk * 4 + 1] * rinv;
        o.z = Oacc[kk * 4 + 2] * rinv;
        o.w = Oacc[kk * 4 + 3] * rinv;
        *(float4*)&O[(baserow + q0 + oqi) * DD + hc + oc * 16 + kk * 4] = o;
    }
}

// ---------------------------------------------------------------------------
extern "C" void kernel_launch(void* const* d_in, const int* in_sizes, int n_in,
                              void* d_out, int out_size)
{
    const float* q  = (const float*)d_in[0];
    const float* k  = (const float*)d_in[1];
    const float* v  = (const float*)d_in[2];
    const float* am = (const float*)d_in[3];
    const float* wq = (const float*)d_in[4];
    const float* bq = (const float*)d_in[5];
    const float* wk = (const float*)d_in[6];
    const float* bk = (const float*)d_in[7];
    const float* wv = (const float*)d_in[8];
    const float* bv = (const float*)d_in[9];
    const float* wo = (const float*)d_in[10];
    const float* bo = (const float*)d_in[11];
    float* out = (float*)d_out;

    float *gQ, *gK, *gV, *gAO;
    cudaGetSymbolAddress((void**)&gQ,  g_Q);
    cudaGetSymbolAddress((void**)&gK,  g_K);
    cudaGetSymbolAddress((void**)&gV,  g_V);
    cudaGetSymbolAddress((void**)&gAO, g_AO);

    dim3 gg(DD / 128, MM / 128);   // 8 x 64 blocks

    sgemm_bias<<<gg, 256>>>(q, wq, bq, gQ, MM, DD, DD);
    sgemm_bias<<<gg, 256>>>(k, wk, bk, gK, MM, DD, DD);
    sgemm_bias<<<gg, 256>>>(v, wv, bv, gV, MM, DD, DD);

    const size_t smem = (size_t)(64*68 + 64*68 + 64*64 + 64*65 + 3*64) * sizeof(float);
    cudaFuncSetAttribute(attn_kernel, cudaFuncAttributeMaxDynamicSharedMemorySize, (int)smem);
    attn_kernel<<<dim3(32, NH, BB), 256, smem>>>(gQ, gK, gV, am, gAO);

    sgemm_bias<<<gg, 256>>>(gAO, wo, bo, out, MM, DD, DD);
}

// round 5
// speedup vs baseline: 1.3422x; 1.3422x over previous
#include <cuda_runtime.h>
#include <cuda_bf16.h>
#include <math.h>
#include <cstdint>

#define BB 4
#define SS 2048
#define DD 1024
#define NH 16
#define DKH 64
#define MM (BB*SS)      // 8192 rows
#define WND 256
#define GLB 16

// ---------------- scratch (__device__ globals, allocation-free rule) -------
__device__ float g_Q[MM*DD];
__device__ float g_K[MM*DD];
__device__ float g_V[MM*DD];
__device__ float g_AO[MM*DD];
__device__ __nv_bfloat16 g_Ah[MM*DD];   // activation hi
__device__ __nv_bfloat16 g_Al[MM*DD];   // activation lo
__device__ __nv_bfloat16 g_Wh[DD*DD];   // weight^T hi
__device__ __nv_bfloat16 g_Wl[DD*DD];   // weight^T lo

// ---------------- helpers ---------------------------------------------------
__device__ __forceinline__ uint32_t smem_to_u32(const void* p) {
    uint32_t a;
    asm("{ .reg .u64 t; cvta.to.shared.u64 t, %1; cvt.u32.u64 %0, t; }" : "=r"(a) : "l"(p));
    return a;
}
__device__ __forceinline__ void cp16(uint32_t dst, const void* src) {
    asm volatile("cp.async.cg.shared.global [%0], [%1], 16;" :: "r"(dst), "l"(src));
}
__device__ __forceinline__ void ldsm_x4(uint32_t& r0, uint32_t& r1, uint32_t& r2, uint32_t& r3, uint32_t a) {
    asm volatile("ldmatrix.sync.aligned.m8n8.x4.shared.b16 {%0,%1,%2,%3}, [%4];"
        : "=r"(r0), "=r"(r1), "=r"(r2), "=r"(r3) : "r"(a));
}
__device__ __forceinline__ void mma16816(float* d, const uint32_t* a, const uint32_t* b) {
    asm volatile("mma.sync.aligned.m16n8k16.row.col.f32.bf16.bf16.f32 "
        "{%0,%1,%2,%3}, {%4,%5,%6,%7}, {%8,%9}, {%0,%1,%2,%3};"
        : "+f"(d[0]), "+f"(d[1]), "+f"(d[2]), "+f"(d[3])
        : "r"(a[0]), "r"(a[1]), "r"(a[2]), "r"(a[3]), "r"(b[0]), "r"(b[1]));
}

// ---------------------------------------------------------------------------
// Conversions
// ---------------------------------------------------------------------------
__global__ void conv_split(const float* __restrict__ X,
                           __nv_bfloat16* __restrict__ hi,
                           __nv_bfloat16* __restrict__ lo)
{
    int idx = (blockIdx.x * 256 + threadIdx.x) * 4;
    float4 x = *(const float4*)(X + idx);
    __nv_bfloat16 h0 = __float2bfloat16(x.x), h1 = __float2bfloat16(x.y);
    __nv_bfloat16 h2 = __float2bfloat16(x.z), h3 = __float2bfloat16(x.w);
    __nv_bfloat162 ph0{h0,h1}, ph1{h2,h3};
    __nv_bfloat162 pl0{__float2bfloat16(x.x - __bfloat162float(h0)),
                       __float2bfloat16(x.y - __bfloat162float(h1))};
    __nv_bfloat162 pl1{__float2bfloat16(x.z - __bfloat162float(h2)),
                       __float2bfloat16(x.w - __bfloat162float(h3))};
    uint2 uh, ul;
    uh.x = *(uint32_t*)&ph0; uh.y = *(uint32_t*)&ph1;
    ul.x = *(uint32_t*)&pl0; ul.y = *(uint32_t*)&pl1;
    *(uint2*)(hi + idx) = uh;
    *(uint2*)(lo + idx) = ul;
}

// W[K=1024][N=1024] -> Wt[N][K] split hi/lo
__global__ void convT_split(const float* __restrict__ W,
                            __nv_bfloat16* __restrict__ hiT,
                            __nv_bfloat16* __restrict__ loT)
{
    __shared__ float t[32][33];
    int bx = blockIdx.x, by = blockIdx.y, tx = threadIdx.x, ty = threadIdx.y;
#pragma unroll
    for (int i = 0; i < 32; i += 8)
        t[ty + i][tx] = W[(by*32 + ty + i) * DD + bx*32 + tx];
    __syncthreads();
#pragma unroll
    for (int i = 0; i < 32; i += 8) {
        float x = t[tx][ty + i];
        __nv_bfloat16 h = __float2bfloat16(x);
        long o = (long)(bx*32 + ty + i) * DD + by*32 + tx;
        hiT[o] = h;
        loT[o] = __float2bfloat16(x - __bfloat162float(h));
    }
}

// ---------------------------------------------------------------------------
// HMMA bf16x3 GEMM: C[M,1024] = (Ah+Al) @ (Bh+Bl)^T + bias
// B stored [N][K] (W^T). 128x128 CTA tile, BK=32, 2-stage cp.async pipeline.
// ---------------------------------------------------------------------------
#define NCHUNK 32
#define STG 32768          // bytes per pipeline stage (4 tiles x 8KB)

__global__ __launch_bounds__(256, 2)
void gemm_hmma(const __nv_bfloat16* __restrict__ Ah, const __nv_bfloat16* __restrict__ Al,
               const __nv_bfloat16* __restrict__ Bh, const __nv_bfloat16* __restrict__ Bl,
               const float* __restrict__ bias, float* __restrict__ C)
{
    extern __shared__ char smem[];
    const uint32_t sb = smem_to_u32(smem);
    const int tid = threadIdx.x, wid = tid >> 5, l = tid & 31;
    const int m0 = blockIdx.y * 128, n0 = blockIdx.x * 128;
    const int wm = wid >> 2, wn = wid & 3;

    // --- loader addressing: 512 16B-chunks per tile, 2 per thread ---
    const int lr = tid >> 2;            // row 0..63 (second chunk: +64)
    const int lc = tid & 3;             // 16B chunk in row
    const uint32_t doff = (uint32_t)lr * 64 + (uint32_t)((lc ^ (lr & 3)) << 4);
    // (lr+64)&3 == lr&3  ->  second chunk dst = doff + 4096
    const __nv_bfloat16* pAh = Ah + (long)(m0 + lr) * DD + lc * 8;
    const __nv_bfloat16* pAl = Al + (long)(m0 + lr) * DD + lc * 8;
    const __nv_bfloat16* pBh = Bh + (long)(n0 + lr) * DD + lc * 8;
    const __nv_bfloat16* pBl = Bl + (long)(n0 + lr) * DD + lc * 8;
    const long RSK = (long)64 * DD;     // 64 rows

    float acc[4][4][4];
#pragma unroll
    for (int i = 0; i < 4; i++)
#pragma unroll
        for (int j = 0; j < 4; j++)
#pragma unroll
            for (int x = 0; x < 4; x++) acc[i][j][x] = 0.f;

    // --- compute-lane addressing ---
    const int am = wm * 64 + (l & 15);          // A row for mt=0
    const int ar3 = am & 3;
    const int ac = l >> 4;                      // A k-chunk add (0/1)
    const int brow = wn * 32 + ((l >> 4) << 3) + (l & 7);  // B row for t2=0
    const int br3 = brow & 3;
    const int bc = (l >> 3) & 1;                // B k-chunk add

    // prologue
    {
        uint32_t st = sb;
        cp16(st + doff,          pAh);  cp16(st + doff + 4096,          pAh + RSK);
        cp16(st + 8192  + doff,  pAl);  cp16(st + 8192  + doff + 4096,  pAl + RSK);
        cp16(st + 16384 + doff,  pBh);  cp16(st + 16384 + doff + 4096,  pBh + RSK);
        cp16(st + 24576 + doff,  pBl);  cp16(st + 24576 + doff + 4096,  pBl + RSK);
        asm volatile("cp.async.commit_group;");
    }

    for (int c = 0; c < NCHUNK; c++) {
        if (c + 1 < NCHUNK) {
            const int ko = (c + 1) * 32;
            uint32_t st = sb + ((c + 1) & 1) * STG;
            cp16(st + doff,          pAh + ko);  cp16(st + doff + 4096,          pAh + ko + RSK);
            cp16(st + 8192  + doff,  pAl + ko);  cp16(st + 8192  + doff + 4096,  pAl + ko + RSK);
            cp16(st + 16384 + doff,  pBh + ko);  cp16(st + 16384 + doff + 4096,  pBh + ko + RSK);
            cp16(st + 24576 + doff,  pBl + ko);  cp16(st + 24576 + doff + 4096,  pBl + ko + RSK);
            asm volatile("cp.async.commit_group;");
            asm volatile("cp.async.wait_group 1;");
        } else {
            asm volatile("cp.async.wait_group 0;");
        }
        __syncthreads();

        const uint32_t base = sb + (c & 1) * STG;
#pragma unroll
        for (int s = 0; s < 2; s++) {
            const uint32_t achk = (uint32_t)((s * 2 + ac) ^ ar3) << 4;
            const uint32_t bchk = (uint32_t)((s * 2 + bc) ^ br3) << 4;
            const uint32_t aaddr = base + (uint32_t)am * 64 + achk;          // A_hi region
            const uint32_t baddr = base + 16384 + (uint32_t)brow * 64 + bchk; // B_hi region

            uint32_t ah[4][4], bh[8], bl[8], al[4][4];
#pragma unroll
            for (int mt = 0; mt < 4; mt++)
                ldsm_x4(ah[mt][0], ah[mt][1], ah[mt][2], ah[mt][3], aaddr + mt * 1024);
            ldsm_x4(bh[0], bh[1], bh[2], bh[3], baddr);
            ldsm_x4(bh[4], bh[5], bh[6], bh[7], baddr + 1024);
#pragma unroll
            for (int mt = 0; mt < 4; mt++)
#pragma unroll
                for (int nt = 0; nt < 4; nt++)
                    mma16816(acc[mt][nt], ah[mt], &bh[nt * 2]);

            // hi * lo
            ldsm_x4(bl[0], bl[1], bl[2], bl[3], baddr + 8192);
            ldsm_x4(bl[4], bl[5], bl[6], bl[7], baddr + 8192 + 1024);
#pragma unroll
            for (int mt = 0; mt < 4; mt++)
#pragma unroll
                for (int nt = 0; nt < 4; nt++)
                    mma16816(acc[mt][nt], ah[mt], &bl[nt * 2]);

            // lo * hi
#pragma unroll
            for (int mt = 0; mt < 4; mt++)
                ldsm_x4(al[mt][0], al[mt][1], al[mt][2], al[mt][3], aaddr + 8192 + mt * 1024);
#pragma unroll
            for (int mt = 0; mt < 4; mt++)
#pragma unroll
                for (int nt = 0; nt < 4; nt++)
                    mma16816(acc[mt][nt], al[mt], &bh[nt * 2]);
        }
        __syncthreads();
    }

    // --- epilogue ---
    const int erow = l >> 2, ecol = (l & 3) * 2;
#pragma unroll
    for (int mt = 0; mt < 4; mt++) {
        const long rg = m0 + wm * 64 + mt * 16 + erow;
#pragma unroll
        for (int nt = 0; nt < 4; nt++) {
            const int cg = n0 + wn * 32 + nt * 8 + ecol;
            const float b0 = bias[cg], b1 = bias[cg + 1];
            float2 o0{acc[mt][nt][0] + b0, acc[mt][nt][1] + b1};
            float2 o1{acc[mt][nt][2] + b0, acc[mt][nt][3] + b1};
            *(float2*)&C[rg * DD + cg]       = o0;
            *(float2*)&C[(rg + 8) * DD + cg] = o1;
        }
    }
}

// ---------------------------------------------------------------------------
// Sparse flash attention (local window + global tokens), fp32 — unchanged.
// ---------------------------------------------------------------------------
__global__ __launch_bounds__(256)
void attn_kernel(const float* __restrict__ Q, const float* __restrict__ K,
                 const float* __restrict__ V, const float* __restrict__ amask,
                 float* __restrict__ O)
{
    extern __shared__ float sm[];
    float* Qs   = sm;
    float* Ks   = Qs + 64 * 68;
    float* Vs   = Ks + 64 * 68;
    float* Ssm  = Vs + 64 * 64;
    float* rowm = Ssm + 64 * 65;
    float* rowl = rowm + 64;
    float* rowsc = rowl + 64;

    const int tid = threadIdx.x;
    const int qt = blockIdx.x, h = blockIdx.y, b = blockIdx.z;
    const int q0 = qt * 64;
    const long baserow = (long)b * SS;
    const int hc = h * DKH;

    for (int idx = tid; idx < 64 * 16; idx += 256) {
        int qi = idx >> 4, kk = idx & 15;
        float4 v4 = *(const float4*)&Q[(baserow + q0 + qi) * DD + hc + kk * 4];
        v4.x *= 0.125f; v4.y *= 0.125f; v4.z *= 0.125f; v4.w *= 0.125f;
        *(float4*)&Qs[qi * 68 + kk * 4] = v4;
    }
    if (tid < 64) { rowm[tid] = -INFINITY; rowl[tid] = 0.f; }

    float Oacc[16];
#pragma unroll
    for (int u = 0; u < 16; u++) Oacc[u] = 0.f;

    const int qg  = tid >> 4;
    const int jg  = tid & 15;
    const int oqi = tid >> 2;
    const int oc  = tid & 3;

    const int jt_lo = max(0, (q0 - WND) >> 6);
    const int jt_hi = min(31, (q0 + 63 + WND) >> 6);

    __syncthreads();

    for (int jt = 0; jt < 32; jt++) {
        bool active = (qt == 0) || (jt == 0) || (jt >= jt_lo && jt <= jt_hi);
        if (!active) continue;
        const int j0 = jt * 64;

        for (int idx = tid; idx < 64 * 16; idx += 256) {
            int ji = idx >> 4, kk = idx & 15;
            *(float4*)&Ks[ji * 68 + kk * 4] =
                *(const float4*)&K[(baserow + j0 + ji) * DD + hc + kk * 4];
            *(float4*)&Vs[ji * 64 + kk * 4] =
                *(const float4*)&V[(baserow + j0 + ji) * DD + hc + kk * 4];
        }
        __syncthreads();

        float accS[4][4];
#pragma unroll
        for (int a = 0; a < 4; a++)
#pragma unroll
            for (int c = 0; c < 4; c++) accS[a][c] = 0.f;

#pragma unroll 4
        for (int kk = 0; kk < 16; kk++) {
            float4 qv[4], kv[4];
#pragma unroll
            for (int a = 0; a < 4; a++)
                qv[a] = *(const float4*)&Qs[(qg * 4 + a) * 68 + kk * 4];
#pragma unroll
            for (int c = 0; c < 4; c++)
                kv[c] = *(const float4*)&Ks[(jg * 4 + c) * 68 + kk * 4];
#pragma unroll
            for (int a = 0; a < 4; a++)
#pragma unroll
                for (int c = 0; c < 4; c++) {
                    accS[a][c] = fmaf(qv[a].x, kv[c].x, accS[a][c]);
                    accS[a][c] = fmaf(qv[a].y, kv[c].y, accS[a][c]);
                    accS[a][c] = fmaf(qv[a].z, kv[c].z, accS[a][c]);
                    accS[a][c] = fmaf(qv[a].w, kv[c].w, accS[a][c]);
                }
        }

        float mv[4];
#pragma unroll
        for (int c = 0; c < 4; c++)
            mv[c] = amask[b * SS + j0 + jg * 4 + c];
#pragma unroll
        for (int a = 0; a < 4; a++) {
            int i = q0 + qg * 4 + a;
#pragma unroll
            for (int c = 0; c < 4; c++) {
                int j = j0 + jg * 4 + c;
                bool ok = (i < GLB) || (j < GLB) || (abs(i - j) <= WND);
                float s = ok ? (accS[a][c] + mv[c]) : -1e30f;
                Ssm[(qg * 4 + a) * 65 + (jg * 4 + c)] = s;
            }
        }
        __syncthreads();

        if (tid < 64) {
            int rr = tid;
            float mold = rowm[rr];
            float mmax = mold;
#pragma unroll 8
            for (int j = 0; j < 64; j++) mmax = fmaxf(mmax, Ssm[rr * 65 + j]);
            float sc = __expf(mold - mmax);
            float lsum = 0.f;
#pragma unroll 8
            for (int j = 0; j < 64; j++) {
                float p = __expf(Ssm[rr * 65 + j] - mmax);
                Ssm[rr * 65 + j] = p;
                lsum += p;
            }
            rowm[rr] = mmax;
            rowl[rr] = rowl[rr] * sc + lsum;
            rowsc[rr] = sc;
        }
        __syncthreads();

        {
            float sc = rowsc[oqi];
#pragma unroll
            for (int u = 0; u < 16; u++) Oacc[u] *= sc;
#pragma unroll 4
            for (int j = 0; j < 64; j++) {
                float p = Ssm[oqi * 65 + j];
#pragma unroll
                for (int kk = 0; kk < 4; kk++) {
                    float4 vv = *(const float4*)&Vs[j * 64 + oc * 16 + kk * 4];
                    Oacc[kk * 4 + 0] = fmaf(p, vv.x, Oacc[kk * 4 + 0]);
                    Oacc[kk * 4 + 1] = fmaf(p, vv.y, Oacc[kk * 4 + 1]);
                    Oacc[kk * 4 + 2] = fmaf(p, vv.z, Oacc[kk * 4 + 2]);
                    Oacc[kk * 4 + 3] = fmaf(p, vv.w, Oacc[kk * 4 + 3]);
                }
            }
        }
        __syncthreads();
    }

    float rinv = 1.f / rowl[oqi];
#pragma unroll
    for (int kk = 0; kk < 4; kk++) {
        float4 o;
        o.x = Oacc[kk * 4 + 0] * rinv;
        o.y = Oacc[kk * 4 + 1] * rinv;
        o.z = Oacc[kk * 4 + 2] * rinv;
        o.w = Oacc[kk * 4 + 3] * rinv;
        *(float4*)&O[(baserow + q0 + oqi) * DD + hc + oc * 16 + kk * 4] = o;
    }
}

// ---------------------------------------------------------------------------
extern "C" void kernel_launch(void* const* d_in, const int* in_sizes, int n_in,
                              void* d_out, int out_size)
{
    const float* q  = (const float*)d_in[0];
    const float* k  = (const float*)d_in[1];
    const float* v  = (const float*)d_in[2];
    const float* am = (const float*)d_in[3];
    const float* wq = (const float*)d_in[4];
    const float* bq = (const float*)d_in[5];
    const float* wk = (const float*)d_in[6];
    const float* bk = (const float*)d_in[7];
    const float* wv = (const float*)d_in[8];
    const float* bv = (const float*)d_in[9];
    const float* wo = (const float*)d_in[10];
    const float* bo = (const float*)d_in[11];
    float* out = (float*)d_out;

    float *gQ, *gK, *gV, *gAO;
    __nv_bfloat16 *gAh, *gAl, *gWh, *gWl;
    cudaGetSymbolAddress((void**)&gQ,  g_Q);
    cudaGetSymbolAddress((void**)&gK,  g_K);
    cudaGetSymbolAddress((void**)&gV,  g_V);
    cudaGetSymbolAddress((void**)&gAO, g_AO);
    cudaGetSymbolAddress((void**)&gAh, g_Ah);
    cudaGetSymbolAddress((void**)&gAl, g_Al);
    cudaGetSymbolAddress((void**)&gWh, g_Wh);
    cudaGetSymbolAddress((void**)&gWl, g_Wl);

    const int convBlocks = (MM * DD) / (256 * 4);     // 8192
    const dim3 tGrid(32, 32), tBlk(32, 8);
    const dim3 gGrid(DD / 128, MM / 128);             // 8 x 64
    const size_t gsmem = 2 * STG;                     // 64 KB
    cudaFuncSetAttribute(gemm_hmma, cudaFuncAttributeMaxDynamicSharedMemorySize, (int)gsmem);

    // Q projection
    convT_split<<<tGrid, tBlk>>>(wq, gWh, gWl);
    conv_split<<<convBlocks, 256>>>(q, gAh, gAl);
    gemm_hmma<<<gGrid, 256, gsmem>>>(gAh, gAl, gWh, gWl, bq, gQ);
    // K projection
    convT_split<<<tGrid, tBlk>>>(wk, gWh, gWl);
    conv_split<<<convBlocks, 256>>>(k, gAh, gAl);
    gemm_hmma<<<gGrid, 256, gsmem>>>(gAh, gAl, gWh, gWl, bk, gK);
    // V projection
    convT_split<<<tGrid, tBlk>>>(wv, gWh, gWl);
    conv_split<<<convBlocks, 256>>>(v, gAh, gAl);
    gemm_hmma<<<gGrid, 256, gsmem>>>(gAh, gAl, gWh, gWl, bv, gV);

    // attention
    const size_t asmem = (size_t)(64*68 + 64*68 + 64*64 + 64*65 + 3*64) * sizeof(float);
    cudaFuncSetAttribute(attn_kernel, cudaFuncAttributeMaxDynamicSharedMemorySize, (int)asmem);
    attn_kernel<<<dim3(32, NH, BB), 256, asmem>>>(gQ, gK, gV, am, gAO);

    // output projection
    convT_split<<<tGrid, tBlk>>>(wo, gWh, gWl);
    conv_split<<<convBlocks, 256>>>(gAO, gAh, gAl);
    gemm_hmma<<<gGrid, 256, gsmem>>>(gAh, gAl, gWh, gWl, bo, out);
}

// round 9
// speedup vs baseline: 4.1781x; 3.1129x over previous
#include <cuda_runtime.h>
#include <cuda_bf16.h>
#include <math.h>
#include <cstdint>

#define BB 4
#define SS 2048
#define DD 1024
#define NH 16
#define DKH 64
#define MM (BB*SS)      // 8192 rows
#define WND 256
#define GLB 16

// ---------------- scratch (__device__ globals, allocation-free rule) -------
__device__ __nv_bfloat16 g_Ah[MM*DD];   // GEMM activation hi
__device__ __nv_bfloat16 g_Al[MM*DD];   // GEMM activation lo
__device__ __nv_bfloat16 g_Wh[DD*DD];   // weight^T hi
__device__ __nv_bfloat16 g_Wl[DD*DD];   // weight^T lo
__device__ __nv_bfloat16 g_Qh[MM*DD], g_Ql[MM*DD];
__device__ __nv_bfloat16 g_Kh[MM*DD], g_Kl[MM*DD];
__device__ __nv_bfloat16 g_Vh[MM*DD], g_Vl[MM*DD];
__device__ __nv_bfloat16 g_AOh[MM*DD], g_AOl[MM*DD];

// ---------------- helpers ---------------------------------------------------
__device__ __forceinline__ uint32_t smem_to_u32(const void* p) {
    uint32_t a;
    asm("{ .reg .u64 t; cvta.to.shared.u64 t, %1; cvt.u32.u64 %0, t; }" : "=r"(a) : "l"(p));
    return a;
}
__device__ __forceinline__ void cp16(uint32_t dst, const void* src) {
    asm volatile("cp.async.cg.shared.global [%0], [%1], 16;" :: "r"(dst), "l"(src));
}
__device__ __forceinline__ void ldsm_x4(uint32_t& r0, uint32_t& r1, uint32_t& r2, uint32_t& r3, uint32_t a) {
    asm volatile("ldmatrix.sync.aligned.m8n8.x4.shared.b16 {%0,%1,%2,%3}, [%4];"
        : "=r"(r0), "=r"(r1), "=r"(r2), "=r"(r3) : "r"(a));
}
__device__ __forceinline__ void ldsm_x4_t(uint32_t& r0, uint32_t& r1, uint32_t& r2, uint32_t& r3, uint32_t a) {
    asm volatile("ldmatrix.sync.aligned.m8n8.x4.trans.shared.b16 {%0,%1,%2,%3}, [%4];"
        : "=r"(r0), "=r"(r1), "=r"(r2), "=r"(r3) : "r"(a));
}
__device__ __forceinline__ void mma16816(float* d, const uint32_t* a, const uint32_t* b) {
    asm volatile("mma.sync.aligned.m16n8k16.row.col.f32.bf16.bf16.f32 "
        "{%0,%1,%2,%3}, {%4,%5,%6,%7}, {%8,%9}, {%0,%1,%2,%3};"
        : "+f"(d[0]), "+f"(d[1]), "+f"(d[2]), "+f"(d[3])
        : "r"(a[0]), "r"(a[1]), "r"(a[2]), "r"(a[3]), "r"(b[0]), "r"(b[1]));
}
// split two fp32 into packed bf16x2 hi + residual lo (elem0 -> low half)
__device__ __forceinline__ void split2(float p0, float p1, uint32_t& hi, uint32_t& lo) {
    __nv_bfloat16 h0 = __float2bfloat16(p0), h1 = __float2bfloat16(p1);
    __nv_bfloat162 hh; hh.x = h0; hh.y = h1;
    hi = *(uint32_t*)&hh;
    __nv_bfloat162 ll;
    ll.x = __float2bfloat16(p0 - __bfloat162float(h0));
    ll.y = __float2bfloat16(p1 - __bfloat162float(h1));
    lo = *(uint32_t*)&ll;
}

// ---------------------------------------------------------------------------
// Conversions
// ---------------------------------------------------------------------------
__global__ void conv_split(const float* __restrict__ X,
                           __nv_bfloat16* __restrict__ hi,
                           __nv_bfloat16* __restrict__ lo)
{
    int idx = (blockIdx.x * 256 + threadIdx.x) * 4;
    float4 x = *(const float4*)(X + idx);
    uint32_t h0, l0, h1, l1;
    split2(x.x, x.y, h0, l0);
    split2(x.z, x.w, h1, l1);
    uint2 uh{h0, h1}, ul{l0, l1};
    *(uint2*)(hi + idx) = uh;
    *(uint2*)(lo + idx) = ul;
}

// W[K=1024][N=1024] -> Wt[N][K] split hi/lo
__global__ void convT_split(const float* __restrict__ W,
                            __nv_bfloat16* __restrict__ hiT,
                            __nv_bfloat16* __restrict__ loT)
{
    __shared__ float t[32][33];
    int bx = blockIdx.x, by = blockIdx.y, tx = threadIdx.x, ty = threadIdx.y;
#pragma unroll
    for (int i = 0; i < 32; i += 8)
        t[ty + i][tx] = W[(by*32 + ty + i) * DD + bx*32 + tx];
    __syncthreads();
#pragma unroll
    for (int i = 0; i < 32; i += 8) {
        float x = t[tx][ty + i];
        __nv_bfloat16 h = __float2bfloat16(x);
        long o = (long)(bx*32 + ty + i) * DD + by*32 + tx;
        hiT[o] = h;
        loT[o] = __float2bfloat16(x - __bfloat162float(h));
    }
}

// ---------------------------------------------------------------------------
// HMMA bf16x3 GEMM: C = (Ah+Al) @ (Bh+Bl)^T + bias
// SPLIT=true: write bf16 hi/lo pair. SPLIT=false: write fp32.
// ---------------------------------------------------------------------------
#define NCHUNK 32
#define STG 32768

template<bool SPLIT>
__global__ __launch_bounds__(256, 2)
void gemm_hmma(const __nv_bfloat16* __restrict__ Ah, const __nv_bfloat16* __restrict__ Al,
               const __nv_bfloat16* __restrict__ Bh, const __nv_bfloat16* __restrict__ Bl,
               const float* __restrict__ bias, float* __restrict__ C,
               __nv_bfloat16* __restrict__ Ch, __nv_bfloat16* __restrict__ Cl)
{
    extern __shared__ char smem[];
    const uint32_t sb = smem_to_u32(smem);
    const int tid = threadIdx.x, wid = tid >> 5, l = tid & 31;
    const int m0 = blockIdx.y * 128, n0 = blockIdx.x * 128;
    const int wm = wid >> 2, wn = wid & 3;

    const int lr = tid >> 2;
    const int lc = tid & 3;
    const uint32_t doff = (uint32_t)lr * 64 + (uint32_t)((lc ^ (lr & 3)) << 4);
    const __nv_bfloat16* pAh = Ah + (long)(m0 + lr) * DD + lc * 8;
    const __nv_bfloat16* pAl = Al + (long)(m0 + lr) * DD + lc * 8;
    const __nv_bfloat16* pBh = Bh + (long)(n0 + lr) * DD + lc * 8;
    const __nv_bfloat16* pBl = Bl + (long)(n0 + lr) * DD + lc * 8;
    const long RSK = (long)64 * DD;

    float acc[4][4][4];
#pragma unroll
    for (int i = 0; i < 4; i++)
#pragma unroll
        for (int j = 0; j < 4; j++)
#pragma unroll
            for (int x = 0; x < 4; x++) acc[i][j][x] = 0.f;

    const int am = wm * 64 + (l & 15);
    const int ar3 = am & 3;
    const int ac = l >> 4;
    const int brow = wn * 32 + ((l >> 4) << 3) + (l & 7);
    const int br3 = brow & 3;
    const int bc = (l >> 3) & 1;

    {
        uint32_t st = sb;
        cp16(st + doff,          pAh);  cp16(st + doff + 4096,          pAh + RSK);
        cp16(st + 8192  + doff,  pAl);  cp16(st + 8192  + doff + 4096,  pAl + RSK);
        cp16(st + 16384 + doff,  pBh);  cp16(st + 16384 + doff + 4096,  pBh + RSK);
        cp16(st + 24576 + doff,  pBl);  cp16(st + 24576 + doff + 4096,  pBl + RSK);
        asm volatile("cp.async.commit_group;");
    }

    for (int c = 0; c < NCHUNK; c++) {
        if (c + 1 < NCHUNK) {
            const int ko = (c + 1) * 32;
            uint32_t st = sb + ((c + 1) & 1) * STG;
            cp16(st + doff,          pAh + ko);  cp16(st + doff + 4096,          pAh + ko + RSK);
            cp16(st + 8192  + doff,  pAl + ko);  cp16(st + 8192  + doff + 4096,  pAl + ko + RSK);
            cp16(st + 16384 + doff,  pBh + ko);  cp16(st + 16384 + doff + 4096,  pBh + ko + RSK);
            cp16(st + 24576 + doff,  pBl + ko);  cp16(st + 24576 + doff + 4096,  pBl + ko + RSK);
            asm volatile("cp.async.commit_group;");
            asm volatile("cp.async.wait_group 1;");
        } else {
            asm volatile("cp.async.wait_group 0;");
        }
        __syncthreads();

        const uint32_t base = sb + (c & 1) * STG;
#pragma unroll
        for (int s = 0; s < 2; s++) {
            const uint32_t achk = (uint32_t)((s * 2 + ac) ^ ar3) << 4;
            const uint32_t bchk = (uint32_t)((s * 2 + bc) ^ br3) << 4;
            const uint32_t aaddr = base + (uint32_t)am * 64 + achk;
            const uint32_t baddr = base + 16384 + (uint32_t)brow * 64 + bchk;

            uint32_t ah[4][4], bh[8], bl[8], al[4][4];
#pragma unroll
            for (int mt = 0; mt < 4; mt++)
                ldsm_x4(ah[mt][0], ah[mt][1], ah[mt][2], ah[mt][3], aaddr + mt * 1024);
            ldsm_x4(bh[0], bh[1], bh[2], bh[3], baddr);
            ldsm_x4(bh[4], bh[5], bh[6], bh[7], baddr + 1024);
#pragma unroll
            for (int mt = 0; mt < 4; mt++)
#pragma unroll
                for (int nt = 0; nt < 4; nt++)
                    mma16816(acc[mt][nt], ah[mt], &bh[nt * 2]);

            ldsm_x4(bl[0], bl[1], bl[2], bl[3], baddr + 8192);
            ldsm_x4(bl[4], bl[5], bl[6], bl[7], baddr + 8192 + 1024);
#pragma unroll
            for (int mt = 0; mt < 4; mt++)
#pragma unroll
                for (int nt = 0; nt < 4; nt++)
                    mma16816(acc[mt][nt], ah[mt], &bl[nt * 2]);

#pragma unroll
            for (int mt = 0; mt < 4; mt++)
                ldsm_x4(al[mt][0], al[mt][1], al[mt][2], al[mt][3], aaddr + 8192 + mt * 1024);
#pragma unroll
            for (int mt = 0; mt < 4; mt++)
#pragma unroll
                for (int nt = 0; nt < 4; nt++)
                    mma16816(acc[mt][nt], al[mt], &bh[nt * 2]);
        }
        __syncthreads();
    }

    const int erow = l >> 2, ecol = (l & 3) * 2;
#pragma unroll
    for (int mt = 0; mt < 4; mt++) {
        const long rg = m0 + wm * 64 + mt * 16 + erow;
#pragma unroll
        for (int nt = 0; nt < 4; nt++) {
            const int cg = n0 + wn * 32 + nt * 8 + ecol;
            const float b0 = bias[cg], b1 = bias[cg + 1];
            float v0 = acc[mt][nt][0] + b0, v1 = acc[mt][nt][1] + b1;
            float v2 = acc[mt][nt][2] + b0, v3 = acc[mt][nt][3] + b1;
            if (SPLIT) {
                uint32_t h0, l0, h1, l1;
                split2(v0, v1, h0, l0);
                split2(v2, v3, h1, l1);
                *(uint32_t*)&Ch[rg * DD + cg]       = h0;
                *(uint32_t*)&Cl[rg * DD + cg]       = l0;
                *(uint32_t*)&Ch[(rg + 8) * DD + cg] = h1;
                *(uint32_t*)&Cl[(rg + 8) * DD + cg] = l1;
            } else {
                float2 o0{v0, v1}, o1{v2, v3};
                *(float2*)&C[rg * DD + cg]       = o0;
                *(float2*)&C[(rg + 8) * DD + cg] = o1;
            }
        }
    }
}

// ---------------------------------------------------------------------------
// HMMA sparse flash attention. 64q per CTA, 4 warps x 16 rows.
// bf16x3 QK^T and PV, fp32 softmax in accumulator fragments.
// smem: Q hi/lo 16KB + 2 stages x (Kh,Kl,Vh,Vl) 32KB = 80KB
// ---------------------------------------------------------------------------
#define ASTG 32768

__global__ __launch_bounds__(128)
void attn_hmma(const __nv_bfloat16* __restrict__ Qh, const __nv_bfloat16* __restrict__ Ql,
               const __nv_bfloat16* __restrict__ Kh, const __nv_bfloat16* __restrict__ Kl,
               const __nv_bfloat16* __restrict__ Vh, const __nv_bfloat16* __restrict__ Vl,
               const float* __restrict__ amask,
               __nv_bfloat16* __restrict__ Oh, __nv_bfloat16* __restrict__ Ol)
{
    extern __shared__ char smem[];
    const uint32_t sb = smem_to_u32(smem);
    const int tid = threadIdx.x, wid = tid >> 5, l = tid & 31;
    const int qt = blockIdx.x, h = blockIdx.y, b = blockIdx.z;
    const int q0 = qt * 64;
    const long baserow = (long)b * SS;
    const int hc = h * DKH;

    // ---- build active tile list ----
    int tiles[32], nlist = 0;
    const int jt_lo = max(0, (q0 - WND) >> 6);
    const int jt_hi = min(31, (q0 + 63 + WND) >> 6);
    if (qt == 0) {
        nlist = 32;
#pragma unroll 8
        for (int i = 0; i < 32; i++) tiles[i] = i;
    } else {
        if (jt_lo > 0) tiles[nlist++] = 0;
        for (int jt = jt_lo; jt <= jt_hi; jt++) tiles[nlist++] = jt;
    }

    // ---- async load Q tile (group 0) ----
    {
        const int row = tid >> 1, cb = (tid & 1) * 4;
        const long src = (baserow + q0 + row) * (long)DD + hc + cb * 8;
        const uint32_t d = sb + row * 128;
#pragma unroll
        for (int i = 0; i < 4; i++) {
            uint32_t off = (uint32_t)(((cb + i) ^ (row & 7)) << 4);
            cp16(d + off, Qh + src + i * 8);
            cp16(d + 8192 + off, Ql + src + i * 8);
        }
        asm volatile("cp.async.commit_group;");
    }
    // ---- async load KV tile 0 (group 1) ----
    const int kvrow = tid >> 1, kvcb = (tid & 1) * 4;
    {
        const long src = (baserow + tiles[0] * 64 + kvrow) * (long)DD + hc + kvcb * 8;
        const uint32_t d = sb + 16384 + kvrow * 128;
#pragma unroll
        for (int i = 0; i < 4; i++) {
            uint32_t off = (uint32_t)(((kvcb + i) ^ (kvrow & 7)) << 4);
            cp16(d + off,         Kh + src + i * 8);
            cp16(d + 8192 + off,  Kl + src + i * 8);
            cp16(d + 16384 + off, Vh + src + i * 8);
            cp16(d + 24576 + off, Vl + src + i * 8);
        }
        asm volatile("cp.async.commit_group;");
    }

    // ---- Q fragments ----
    asm volatile("cp.async.wait_group 1;");
    __syncthreads();
    uint32_t qhf[4][4], qlf[4][4];
    {
        const uint32_t qaddr = sb + (uint32_t)(wid * 16 + (l & 15)) * 128;
#pragma unroll
        for (int ks = 0; ks < 4; ks++) {
            uint32_t off = (uint32_t)(((2 * ks + (l >> 4)) ^ (l & 7)) << 4);
            ldsm_x4(qhf[ks][0], qhf[ks][1], qhf[ks][2], qhf[ks][3], qaddr + off);
            ldsm_x4(qlf[ks][0], qlf[ks][1], qlf[ks][2], qlf[ks][3], qaddr + 8192 + off);
        }
    }

    float Oacc[8][4];
#pragma unroll
    for (int d = 0; d < 8; d++)
#pragma unroll
        for (int x = 0; x < 4; x++) Oacc[d][x] = 0.f;
    float m0 = -INFINITY, m1 = -INFINITY, l0s = 0.f, l1s = 0.f;

    const int i0 = q0 + wid * 16 + (l >> 2);
    const int i1 = i0 + 8;
    const int colq = 2 * (l & 3);
    const uint32_t roff_b = (uint32_t)(((l >> 4) << 3) + (l & 7)) * 128;  // K frag row offset
    const uint32_t roff_v = (uint32_t)((((l >> 3) & 1) << 3) + (l & 7)) * 128; // V frag row offset
    const int l7 = l & 7;

    for (int it = 0; it < nlist; it++) {
        // prefetch next tile
        if (it + 1 < nlist) {
            const long src = (baserow + tiles[it + 1] * 64 + kvrow) * (long)DD + hc + kvcb * 8;
            const uint32_t d = sb + 16384 + ((it + 1) & 1) * ASTG + kvrow * 128;
#pragma unroll
            for (int i = 0; i < 4; i++) {
                uint32_t off = (uint32_t)(((kvcb + i) ^ (kvrow & 7)) << 4);
                cp16(d + off,         Kh + src + i * 8);
                cp16(d + 8192 + off,  Kl + src + i * 8);
                cp16(d + 16384 + off, Vh + src + i * 8);
                cp16(d + 24576 + off, Vl + src + i * 8);
            }
            asm volatile("cp.async.commit_group;");
            asm volatile("cp.async.wait_group 1;");
        } else {
            asm volatile("cp.async.wait_group 0;");
        }
        __syncthreads();

        const int j0 = tiles[it] * 64;
        const uint32_t kb = sb + 16384 + (it & 1) * ASTG;
        const uint32_t vb = kb + 16384;

        // ---- QK^T: S[8 ntiles][4] ----
        float S[8][4];
#pragma unroll
        for (int nt = 0; nt < 8; nt++)
#pragma unroll
            for (int x = 0; x < 4; x++) S[nt][x] = 0.f;

#pragma unroll
        for (int ks = 0; ks < 4; ks++) {
            const uint32_t cslot = (uint32_t)(((2 * ks + ((l >> 3) & 1)) ^ l7) << 4);
            uint32_t bh[16], bl[16];
#pragma unroll
            for (int g = 0; g < 4; g++)
                ldsm_x4(bh[g*4], bh[g*4+1], bh[g*4+2], bh[g*4+3],
                        kb + (uint32_t)(g * 16) * 128 + roff_b + cslot);
#pragma unroll
            for (int g = 0; g < 4; g++)
                ldsm_x4(bl[g*4], bl[g*4+1], bl[g*4+2], bl[g*4+3],
                        kb + 8192 + (uint32_t)(g * 16) * 128 + roff_b + cslot);
#pragma unroll
            for (int nt = 0; nt < 8; nt++) {
                mma16816(S[nt], qhf[ks], &bh[nt * 2]);
                mma16816(S[nt], qhf[ks], &bl[nt * 2]);
                mma16816(S[nt], qlf[ks], &bh[nt * 2]);
            }
        }

        // ---- mask + scale ----
        float t0 = -INFINITY, t1 = -INFINITY;
#pragma unroll
        for (int nt = 0; nt < 8; nt++) {
            const int c0 = j0 + nt * 8 + colq;
            const float a0 = __ldg(&amask[b * SS + c0]);
            const float a1 = __ldg(&amask[b * SS + c0 + 1]);
            bool ok00 = (i0 < GLB) || (c0 < GLB)     || (abs(i0 - c0) <= WND);
            bool ok01 = (i0 < GLB) || (c0 + 1 < GLB) || (abs(i0 - c0 - 1) <= WND);
            bool ok10 = (i1 < GLB) || (c0 < GLB)     || (abs(i1 - c0) <= WND);
            bool ok11 = (i1 < GLB) || (c0 + 1 < GLB) || (abs(i1 - c0 - 1) <= WND);
            S[nt][0] = ok00 ? S[nt][0] * 0.125f + a0 : -1e30f;
            S[nt][1] = ok01 ? S[nt][1] * 0.125f + a1 : -1e30f;
            S[nt][2] = ok10 ? S[nt][2] * 0.125f + a0 : -1e30f;
            S[nt][3] = ok11 ? S[nt][3] * 0.125f + a1 : -1e30f;
            t0 = fmaxf(t0, fmaxf(S[nt][0], S[nt][1]));
            t1 = fmaxf(t1, fmaxf(S[nt][2], S[nt][3]));
        }
        t0 = fmaxf(t0, __shfl_xor_sync(0xffffffffu, t0, 1));
        t0 = fmaxf(t0, __shfl_xor_sync(0xffffffffu, t0, 2));
        t1 = fmaxf(t1, __shfl_xor_sync(0xffffffffu, t1, 1));
        t1 = fmaxf(t1, __shfl_xor_sync(0xffffffffu, t1, 2));

        const float m0n = fmaxf(m0, t0), m1n = fmaxf(m1, t1);
        const float sc0 = __expf(m0 - m0n), sc1 = __expf(m1 - m1n);
        m0 = m0n; m1 = m1n;

        float s0 = 0.f, s1 = 0.f;
#pragma unroll
        for (int nt = 0; nt < 8; nt++) {
            S[nt][0] = __expf(S[nt][0] - m0);
            S[nt][1] = __expf(S[nt][1] - m0);
            S[nt][2] = __expf(S[nt][2] - m1);
            S[nt][3] = __expf(S[nt][3] - m1);
            s0 += S[nt][0] + S[nt][1];
            s1 += S[nt][2] + S[nt][3];
        }
        s0 += __shfl_xor_sync(0xffffffffu, s0, 1);
        s0 += __shfl_xor_sync(0xffffffffu, s0, 2);
        s1 += __shfl_xor_sync(0xffffffffu, s1, 1);
        s1 += __shfl_xor_sync(0xffffffffu, s1, 2);
        l0s = l0s * sc0 + s0;
        l1s = l1s * sc1 + s1;

#pragma unroll
        for (int d = 0; d < 8; d++) {
            Oacc[d][0] *= sc0; Oacc[d][1] *= sc0;
            Oacc[d][2] *= sc1; Oacc[d][3] *= sc1;
        }

        // ---- P @ V ----
#pragma unroll
        for (int ks = 0; ks < 4; ks++) {
            uint32_t ph[4], pl[4];
            split2(S[2*ks][0],   S[2*ks][1],   ph[0], pl[0]);
            split2(S[2*ks][2],   S[2*ks][3],   ph[1], pl[1]);
            split2(S[2*ks+1][0], S[2*ks+1][1], ph[2], pl[2]);
            split2(S[2*ks+1][2], S[2*ks+1][3], ph[3], pl[3]);

            const uint32_t vrow = vb + (uint32_t)(ks * 16) * 128 + roff_v;
            uint32_t vh[16], vl[16];
#pragma unroll
            for (int dg = 0; dg < 4; dg++) {
                uint32_t dslot = (uint32_t)(((2 * dg + (l >> 4)) ^ l7) << 4);
                ldsm_x4_t(vh[dg*4], vh[dg*4+1], vh[dg*4+2], vh[dg*4+3], vrow + dslot);
            }
#pragma unroll
            for (int dg = 0; dg < 4; dg++) {
                uint32_t dslot = (uint32_t)(((2 * dg + (l >> 4)) ^ l7) << 4);
                ldsm_x4_t(vl[dg*4], vl[dg*4+1], vl[dg*4+2], vl[dg*4+3], vrow + 8192 + dslot);
            }
#pragma unroll
            for (int dt = 0; dt < 8; dt++) {
                mma16816(Oacc[dt], ph, &vh[dt * 2]);
                mma16816(Oacc[dt], ph, &vl[dt * 2]);
                mma16816(Oacc[dt], pl, &vh[dt * 2]);
            }
        }
        __syncthreads();
    }

    // ---- normalize + write bf16 hi/lo ----
    const float r0 = 1.f / l0s, r1 = 1.f / l1s;
    const long row0 = baserow + i0;   // i0 = q0 + wid*16 + (l>>2) global q index
    const long row1 = row0 + 8;
#pragma unroll
    for (int dt = 0; dt < 8; dt++) {
        const int col = hc + dt * 8 + colq;
        uint32_t h0, lo0, h1, lo1;
        split2(Oacc[dt][0] * r0, Oacc[dt][1] * r0, h0, lo0);
        split2(Oacc[dt][2] * r1, Oacc[dt][3] * r1, h1, lo1);
        *(uint32_t*)&Oh[row0 * DD + col] = h0;
        *(uint32_t*)&Ol[row0 * DD + col] = lo0;
        *(uint32_t*)&Oh[row1 * DD + col] = h1;
        *(uint32_t*)&Ol[row1 * DD + col] = lo1;
    }
}

// ---------------------------------------------------------------------------
extern "C" void kernel_launch(void* const* d_in, const int* in_sizes, int n_in,
                              void* d_out, int out_size)
{
    const float* q  = (const float*)d_in[0];
    const float* k  = (const float*)d_in[1];
    const float* v  = (const float*)d_in[2];
    const float* am = (const float*)d_in[3];
    const float* wq = (const float*)d_in[4];
    const float* bq = (const float*)d_in[5];
    const float* wk = (const float*)d_in[6];
    const float* bk = (const float*)d_in[7];
    const float* wv = (const float*)d_in[8];
    const float* bv = (const float*)d_in[9];
    const float* wo = (const float*)d_in[10];
    const float* bo = (const float*)d_in[11];
    float* out = (float*)d_out;

    __nv_bfloat16 *gAh, *gAl, *gWh, *gWl;
    __nv_bfloat16 *gQh, *gQl, *gKh, *gKl, *gVh, *gVl, *gOh, *gOl;
    cudaGetSymbolAddress((void**)&gAh, g_Ah);
    cudaGetSymbolAddress((void**)&gAl, g_Al);
    cudaGetSymbolAddress((void**)&gWh, g_Wh);
    cudaGetSymbolAddress((void**)&gWl, g_Wl);
    cudaGetSymbolAddress((void**)&gQh, g_Qh);
    cudaGetSymbolAddress((void**)&gQl, g_Ql);
    cudaGetSymbolAddress((void**)&gKh, g_Kh);
    cudaGetSymbolAddress((void**)&gKl, g_Kl);
    cudaGetSymbolAddress((void**)&gVh, g_Vh);
    cudaGetSymbolAddress((void**)&gVl, g_Vl);
    cudaGetSymbolAddress((void**)&gOh, g_AOh);
    cudaGetSymbolAddress((void**)&gOl, g_AOl);

    const int convBlocks = (MM * DD) / (256 * 4);
    const dim3 tGrid(32, 32), tBlk(32, 8);
    const dim3 gGrid(DD / 128, MM / 128);
    const size_t gsmem = 2 * STG;
    cudaFuncSetAttribute(gemm_hmma<true>,  cudaFuncAttributeMaxDynamicSharedMemorySize, (int)gsmem);
    cudaFuncSetAttribute(gemm_hmma<false>, cudaFuncAttributeMaxDynamicSharedMemorySize, (int)gsmem);

    // Q projection -> bf16 hi/lo
    convT_split<<<tGrid, tBlk>>>(wq, gWh, gWl);
    conv_split<<<convBlocks, 256>>>(q, gAh, gAl);
    gemm_hmma<true><<<gGrid, 256, gsmem>>>(gAh, gAl, gWh, gWl, bq, nullptr, gQh, gQl);
    // K projection
    convT_split<<<tGrid, tBlk>>>(wk, gWh, gWl);
    conv_split<<<convBlocks, 256>>>(k, gAh, gAl);
    gemm_hmma<true><<<gGrid, 256, gsmem>>>(gAh, gAl, gWh, gWl, bk, nullptr, gKh, gKl);
    // V projection
    convT_split<<<tGrid, tBlk>>>(wv, gWh, gWl);
    conv_split<<<convBlocks, 256>>>(v, gAh, gAl);
    gemm_hmma<true><<<gGrid, 256, gsmem>>>(gAh, gAl, gWh, gWl, bv, nullptr, gVh, gVl);

    // attention (bf16x3 HMMA flash)
    const size_t asmem = 16384 + 2 * ASTG;   // 80 KB
    cudaFuncSetAttribute(attn_hmma, cudaFuncAttributeMaxDynamicSharedMemorySize, (int)asmem);
    attn_hmma<<<dim3(32, NH, BB), 128, asmem>>>(gQh, gQl, gKh, gKl, gVh, gVl, am, gOh, gOl);

    // output projection -> fp32
    convT_split<<<tGrid, tBlk>>>(wo, gWh, gWl);
    gemm_hmma<false><<<gGrid, 256, gsmem>>>(gOh, gOl, gWh, gWl, bo, out, nullptr, nullptr);
}

// round 10
// speedup vs baseline: 5.7359x; 1.3728x over previous
#include <cuda_runtime.h>
#include <cuda_fp16.h>
#include <math.h>
#include <cstdint>

#define BB 4
#define SS 2048
#define DD 1024
#define NH 16
#define DKH 64
#define MM (BB*SS)      // 8192 rows
#define WND 256
#define GLB 16

// ---------------- scratch (__device__ globals, allocation-free rule) -------
__device__ __half g_A[MM*DD];            // activation (single fp16)
__device__ __half g_Wh[DD*DD], g_Wl[DD*DD];  // weight^T hi/lo
__device__ __half g_Q[MM*DD];            // Q single
__device__ __half g_Kh[MM*DD], g_Kl[MM*DD];
__device__ __half g_Vh[MM*DD], g_Vl[MM*DD];
__device__ __half g_AO[MM*DD];           // attention out single

// ---------------- helpers ---------------------------------------------------
__device__ __forceinline__ uint32_t smem_to_u32(const void* p) {
    uint32_t a;
    asm("{ .reg .u64 t; cvta.to.shared.u64 t, %1; cvt.u32.u64 %0, t; }" : "=r"(a) : "l"(p));
    return a;
}
__device__ __forceinline__ void cp16(uint32_t dst, const void* src) {
    asm volatile("cp.async.cg.shared.global [%0], [%1], 16;" :: "r"(dst), "l"(src));
}
__device__ __forceinline__ void ldsm_x4(uint32_t& r0, uint32_t& r1, uint32_t& r2, uint32_t& r3, uint32_t a) {
    asm volatile("ldmatrix.sync.aligned.m8n8.x4.shared.b16 {%0,%1,%2,%3}, [%4];"
        : "=r"(r0), "=r"(r1), "=r"(r2), "=r"(r3) : "r"(a));
}
__device__ __forceinline__ void ldsm_x4_t(uint32_t& r0, uint32_t& r1, uint32_t& r2, uint32_t& r3, uint32_t a) {
    asm volatile("ldmatrix.sync.aligned.m8n8.x4.trans.shared.b16 {%0,%1,%2,%3}, [%4];"
        : "=r"(r0), "=r"(r1), "=r"(r2), "=r"(r3) : "r"(a));
}
__device__ __forceinline__ void mma16816(float* d, const uint32_t* a, const uint32_t* b) {
    asm volatile("mma.sync.aligned.m16n8k16.row.col.f32.f16.f16.f32 "
        "{%0,%1,%2,%3}, {%4,%5,%6,%7}, {%8,%9}, {%0,%1,%2,%3};"
        : "+f"(d[0]), "+f"(d[1]), "+f"(d[2]), "+f"(d[3])
        : "r"(a[0]), "r"(a[1]), "r"(a[2]), "r"(a[3]), "r"(b[0]), "r"(b[1]));
}
__device__ __forceinline__ uint32_t pack2h(float p0, float p1) {
    __half2 h = __floats2half2_rn(p0, p1);
    return *(uint32_t*)&h;
}
__device__ __forceinline__ void split2h(float p0, float p1, uint32_t& hi, uint32_t& lo) {
    __half h0 = __float2half_rn(p0), h1 = __float2half_rn(p1);
    __half2 hh; hh.x = h0; hh.y = h1;
    hi = *(uint32_t*)&hh;
    __half2 ll;
    ll.x = __float2half_rn(p0 - __half2float(h0));
    ll.y = __float2half_rn(p1 - __half2float(h1));
    lo = *(uint32_t*)&ll;
}

// ---------------------------------------------------------------------------
// Conversions
// ---------------------------------------------------------------------------
__global__ void conv_half(const float* __restrict__ X, __half* __restrict__ Y)
{
    int idx = (blockIdx.x * 256 + threadIdx.x) * 4;
    float4 x = *(const float4*)(X + idx);
    uint2 u{pack2h(x.x, x.y), pack2h(x.z, x.w)};
    *(uint2*)(Y + idx) = u;
}

// W[K][N] -> Wt[N][K] fp16 hi/lo
__global__ void convT_split(const float* __restrict__ W,
                            __half* __restrict__ hiT, __half* __restrict__ loT)
{
    __shared__ float t[32][33];
    int bx = blockIdx.x, by = blockIdx.y, tx = threadIdx.x, ty = threadIdx.y;
#pragma unroll
    for (int i = 0; i < 32; i += 8)
        t[ty + i][tx] = W[(by*32 + ty + i) * DD + bx*32 + tx];
    __syncthreads();
#pragma unroll
    for (int i = 0; i < 32; i += 8) {
        float x = t[tx][ty + i];
        __half h = __float2half_rn(x);
        long o = (long)(bx*32 + ty + i) * DD + by*32 + tx;
        hiT[o] = h;
        loT[o] = __float2half_rn(x - __half2float(h));
    }
}

// ---------------------------------------------------------------------------
// HMMA fp16x2 GEMM: C = A @ (Bh+Bl)^T + bias.  A single fp16, B split.
// OUT: 0 = fp32 C, 1 = half single Ch, 2 = half hi/lo Ch+Cl
// stage: A 8KB @0, Bh 8KB @8192, Bl 8KB @16384
// ---------------------------------------------------------------------------
#define NCHUNK 32
#define STG 24576

template<int OUT>
__global__ __launch_bounds__(256, 2)
void gemm_hmma(const __half* __restrict__ A,
               const __half* __restrict__ Bh, const __half* __restrict__ Bl,
               const float* __restrict__ bias, float* __restrict__ C,
               __half* __restrict__ Ch, __half* __restrict__ Cl)
{
    extern __shared__ char smem[];
    const uint32_t sb = smem_to_u32(smem);
    const int tid = threadIdx.x, wid = tid >> 5, l = tid & 31;
    const int m0 = blockIdx.y * 128, n0 = blockIdx.x * 128;
    const int wm = wid >> 2, wn = wid & 3;

    const int lr = tid >> 2;
    const int lc = tid & 3;
    const uint32_t doff = (uint32_t)lr * 64 + (uint32_t)((lc ^ (lr & 3)) << 4);
    const __half* pA  = A  + (long)(m0 + lr) * DD + lc * 8;
    const __half* pBh = Bh + (long)(n0 + lr) * DD + lc * 8;
    const __half* pBl = Bl + (long)(n0 + lr) * DD + lc * 8;
    const long RSK = (long)64 * DD;

    float acc[4][4][4];
#pragma unroll
    for (int i = 0; i < 4; i++)
#pragma unroll
        for (int j = 0; j < 4; j++)
#pragma unroll
            for (int x = 0; x < 4; x++) acc[i][j][x] = 0.f;

    const int am = wm * 64 + (l & 15);
    const int ar3 = am & 3;
    const int ac = l >> 4;
    const int brow = wn * 32 + ((l >> 4) << 3) + (l & 7);
    const int br3 = brow & 3;
    const int bc = (l >> 3) & 1;

    {
        uint32_t st = sb;
        cp16(st + doff,          pA);   cp16(st + doff + 4096,          pA + RSK);
        cp16(st + 8192  + doff,  pBh);  cp16(st + 8192  + doff + 4096,  pBh + RSK);
        cp16(st + 16384 + doff,  pBl);  cp16(st + 16384 + doff + 4096,  pBl + RSK);
        asm volatile("cp.async.commit_group;");
    }

    for (int c = 0; c < NCHUNK; c++) {
        if (c + 1 < NCHUNK) {
            const int ko = (c + 1) * 32;
            uint32_t st = sb + ((c + 1) & 1) * STG;
            cp16(st + doff,          pA + ko);   cp16(st + doff + 4096,          pA + ko + RSK);
            cp16(st + 8192  + doff,  pBh + ko);  cp16(st + 8192  + doff + 4096,  pBh + ko + RSK);
            cp16(st + 16384 + doff,  pBl + ko);  cp16(st + 16384 + doff + 4096,  pBl + ko + RSK);
            asm volatile("cp.async.commit_group;");
            asm volatile("cp.async.wait_group 1;");
        } else {
            asm volatile("cp.async.wait_group 0;");
        }
        __syncthreads();

        const uint32_t base = sb + (c & 1) * STG;
#pragma unroll
        for (int s = 0; s < 2; s++) {
            const uint32_t achk = (uint32_t)((s * 2 + ac) ^ ar3) << 4;
            const uint32_t bchk = (uint32_t)((s * 2 + bc) ^ br3) << 4;
            const uint32_t aaddr = base + (uint32_t)am * 64 + achk;
            const uint32_t baddr = base + 8192 + (uint32_t)brow * 64 + bchk;

            uint32_t ah[4][4], bh[8], bl[8];
#pragma unroll
            for (int mt = 0; mt < 4; mt++)
                ldsm_x4(ah[mt][0], ah[mt][1], ah[mt][2], ah[mt][3], aaddr + mt * 1024);
            ldsm_x4(bh[0], bh[1], bh[2], bh[3], baddr);
            ldsm_x4(bh[4], bh[5], bh[6], bh[7], baddr + 1024);
#pragma unroll
            for (int mt = 0; mt < 4; mt++)
#pragma unroll
                for (int nt = 0; nt < 4; nt++)
                    mma16816(acc[mt][nt], ah[mt], &bh[nt * 2]);

            ldsm_x4(bl[0], bl[1], bl[2], bl[3], baddr + 8192);
            ldsm_x4(bl[4], bl[5], bl[6], bl[7], baddr + 8192 + 1024);
#pragma unroll
            for (int mt = 0; mt < 4; mt++)
#pragma unroll
                for (int nt = 0; nt < 4; nt++)
                    mma16816(acc[mt][nt], ah[mt], &bl[nt * 2]);
        }
        __syncthreads();
    }

    const int erow = l >> 2, ecol = (l & 3) * 2;
#pragma unroll
    for (int mt = 0; mt < 4; mt++) {
        const long rg = m0 + wm * 64 + mt * 16 + erow;
#pragma unroll
        for (int nt = 0; nt < 4; nt++) {
            const int cg = n0 + wn * 32 + nt * 8 + ecol;
            const float b0 = bias[cg], b1 = bias[cg + 1];
            float v0 = acc[mt][nt][0] + b0, v1 = acc[mt][nt][1] + b1;
            float v2 = acc[mt][nt][2] + b0, v3 = acc[mt][nt][3] + b1;
            if (OUT == 0) {
                float2 o0{v0, v1}, o1{v2, v3};
                *(float2*)&C[rg * DD + cg]       = o0;
                *(float2*)&C[(rg + 8) * DD + cg] = o1;
            } else if (OUT == 1) {
                *(uint32_t*)&Ch[rg * DD + cg]       = pack2h(v0, v1);
                *(uint32_t*)&Ch[(rg + 8) * DD + cg] = pack2h(v2, v3);
            } else {
                uint32_t h0, l0, h1, l1;
                split2h(v0, v1, h0, l0);
                split2h(v2, v3, h1, l1);
                *(uint32_t*)&Ch[rg * DD + cg]       = h0;
                *(uint32_t*)&Cl[rg * DD + cg]       = l0;
                *(uint32_t*)&Ch[(rg + 8) * DD + cg] = h1;
                *(uint32_t*)&Cl[(rg + 8) * DD + cg] = l1;
            }
        }
    }
}

// ---------------------------------------------------------------------------
// HMMA fp16x2 sparse flash attention. 64q per CTA, 4 warps x 16 rows.
// Q single fp16, K/V split hi/lo; 2-pass QK and PV; P single fp16.
// smem: Q 8KB + 2 stages x 32KB (Kh,Kl,Vh,Vl) = 72KB
// ---------------------------------------------------------------------------
#define ASTG 32768

__global__ __launch_bounds__(128)
void attn_hmma(const __half* __restrict__ Q,
               const __half* __restrict__ Kh, const __half* __restrict__ Kl,
               const __half* __restrict__ Vh, const __half* __restrict__ Vl,
               const float* __restrict__ amask, __half* __restrict__ O)
{
    extern __shared__ char smem[];
    const uint32_t sb = smem_to_u32(smem);
    const int tid = threadIdx.x, wid = tid >> 5, l = tid & 31;
    const int qt = blockIdx.x, h = blockIdx.y, b = blockIdx.z;
    const int q0 = qt * 64;
    const long baserow = (long)b * SS;
    const int hc = h * DKH;

    int tiles[32], nlist = 0;
    const int jt_lo = max(0, (q0 - WND) >> 6);
    const int jt_hi = min(31, (q0 + 63 + WND) >> 6);
    if (qt == 0) {
        nlist = 32;
#pragma unroll 8
        for (int i = 0; i < 32; i++) tiles[i] = i;
    } else {
        if (jt_lo > 0) tiles[nlist++] = 0;
        for (int jt = jt_lo; jt <= jt_hi; jt++) tiles[nlist++] = jt;
    }

    // ---- async load Q tile (single fp16, group 0) ----
    {
        const int row = tid >> 1, cb = (tid & 1) * 4;
        const long src = (baserow + q0 + row) * (long)DD + hc + cb * 8;
        const uint32_t d = sb + row * 128;
#pragma unroll
        for (int i = 0; i < 4; i++) {
            uint32_t off = (uint32_t)(((cb + i) ^ (row & 7)) << 4);
            cp16(d + off, Q + src + i * 8);
        }
        asm volatile("cp.async.commit_group;");
    }
    // ---- async load KV tile 0 (group 1) ----
    const int kvrow = tid >> 1, kvcb = (tid & 1) * 4;
    {
        const long src = (baserow + tiles[0] * 64 + kvrow) * (long)DD + hc + kvcb * 8;
        const uint32_t d = sb + 8192 + kvrow * 128;
#pragma unroll
        for (int i = 0; i < 4; i++) {
            uint32_t off = (uint32_t)(((kvcb + i) ^ (kvrow & 7)) << 4);
            cp16(d + off,         Kh + src + i * 8);
            cp16(d + 8192 + off,  Kl + src + i * 8);
            cp16(d + 16384 + off, Vh + src + i * 8);
            cp16(d + 24576 + off, Vl + src + i * 8);
        }
        asm volatile("cp.async.commit_group;");
    }

    asm volatile("cp.async.wait_group 1;");
    __syncthreads();
    uint32_t qf[4][4];
    {
        const uint32_t qaddr = sb + (uint32_t)(wid * 16 + (l & 15)) * 128;
#pragma unroll
        for (int ks = 0; ks < 4; ks++) {
            uint32_t off = (uint32_t)(((2 * ks + (l >> 4)) ^ (l & 7)) << 4);
            ldsm_x4(qf[ks][0], qf[ks][1], qf[ks][2], qf[ks][3], qaddr + off);
        }
    }

    float Oacc[8][4];
#pragma unroll
    for (int d = 0; d < 8; d++)
#pragma unroll
        for (int x = 0; x < 4; x++) Oacc[d][x] = 0.f;
    float m0 = -INFINITY, m1 = -INFINITY, l0s = 0.f, l1s = 0.f;

    const int i0 = q0 + wid * 16 + (l >> 2);
    const int i1 = i0 + 8;
    const int colq = 2 * (l & 3);
    const uint32_t roff_b = (uint32_t)(((l >> 4) << 3) + (l & 7)) * 128;
    const uint32_t roff_v = (uint32_t)((((l >> 3) & 1) << 3) + (l & 7)) * 128;
    const int l7 = l & 7;

    for (int it = 0; it < nlist; it++) {
        if (it + 1 < nlist) {
            const long src = (baserow + tiles[it + 1] * 64 + kvrow) * (long)DD + hc + kvcb * 8;
            const uint32_t d = sb + 8192 + ((it + 1) & 1) * ASTG + kvrow * 128;
#pragma unroll
            for (int i = 0; i < 4; i++) {
                uint32_t off = (uint32_t)(((kvcb + i) ^ (kvrow & 7)) << 4);
                cp16(d + off,         Kh + src + i * 8);
                cp16(d + 8192 + off,  Kl + src + i * 8);
                cp16(d + 16384 + off, Vh + src + i * 8);
                cp16(d + 24576 + off, Vl + src + i * 8);
            }
            asm volatile("cp.async.commit_group;");
            asm volatile("cp.async.wait_group 1;");
        } else {
            asm volatile("cp.async.wait_group 0;");
        }
        __syncthreads();

        const int j0 = tiles[it] * 64;
        const uint32_t kb = sb + 8192 + (it & 1) * ASTG;
        const uint32_t vb = kb + 16384;

        float S[8][4];
#pragma unroll
        for (int nt = 0; nt < 8; nt++)
#pragma unroll
            for (int x = 0; x < 4; x++) S[nt][x] = 0.f;

#pragma unroll
        for (int ks = 0; ks < 4; ks++) {
            const uint32_t cslot = (uint32_t)(((2 * ks + ((l >> 3) & 1)) ^ l7) << 4);
            uint32_t bh[16], bl[16];
#pragma unroll
            for (int g = 0; g < 4; g++)
                ldsm_x4(bh[g*4], bh[g*4+1], bh[g*4+2], bh[g*4+3],
                        kb + (uint32_t)(g * 16) * 128 + roff_b + cslot);
#pragma unroll
            for (int g = 0; g < 4; g++)
                ldsm_x4(bl[g*4], bl[g*4+1], bl[g*4+2], bl[g*4+3],
                        kb + 8192 + (uint32_t)(g * 16) * 128 + roff_b + cslot);
#pragma unroll
            for (int nt = 0; nt < 8; nt++) {
                mma16816(S[nt], qf[ks], &bh[nt * 2]);
                mma16816(S[nt], qf[ks], &bl[nt * 2]);
            }
        }

        float t0 = -INFINITY, t1 = -INFINITY;
#pragma unroll
        for (int nt = 0; nt < 8; nt++) {
            const int c0 = j0 + nt * 8 + colq;
            const float a0 = __ldg(&amask[b * SS + c0]);
            const float a1 = __ldg(&amask[b * SS + c0 + 1]);
            bool ok00 = (i0 < GLB) || (c0 < GLB)     || (abs(i0 - c0) <= WND);
            bool ok01 = (i0 < GLB) || (c0 + 1 < GLB) || (abs(i0 - c0 - 1) <= WND);
            bool ok10 = (i1 < GLB) || (c0 < GLB)     || (abs(i1 - c0) <= WND);
            bool ok11 = (i1 < GLB) || (c0 + 1 < GLB) || (abs(i1 - c0 - 1) <= WND);
            S[nt][0] = ok00 ? S[nt][0] * 0.125f + a0 : -1e30f;
            S[nt][1] = ok01 ? S[nt][1] * 0.125f + a1 : -1e30f;
            S[nt][2] = ok10 ? S[nt][2] * 0.125f + a0 : -1e30f;
            S[nt][3] = ok11 ? S[nt][3] * 0.125f + a1 : -1e30f;
            t0 = fmaxf(t0, fmaxf(S[nt][0], S[nt][1]));
            t1 = fmaxf(t1, fmaxf(S[nt][2], S[nt][3]));
        }
        t0 = fmaxf(t0, __shfl_xor_sync(0xffffffffu, t0, 1));
        t0 = fmaxf(t0, __shfl_xor_sync(0xffffffffu, t0, 2));
        t1 = fmaxf(t1, __shfl_xor_sync(0xffffffffu, t1, 1));
        t1 = fmaxf(t1, __shfl_xor_sync(0xffffffffu, t1, 2));

        const float m0n = fmaxf(m0, t0), m1n = fmaxf(m1, t1);
        const float sc0 = __expf(m0 - m0n), sc1 = __expf(m1 - m1n);
        m0 = m0n; m1 = m1n;

        float s0 = 0.f, s1 = 0.f;
#pragma unroll
        for (int nt = 0; nt < 8; nt++) {
            S[nt][0] = __expf(S[nt][0] - m0);
            S[nt][1] = __expf(S[nt][1] - m0);
            S[nt][2] = __expf(S[nt][2] - m1);
            S[nt][3] = __expf(S[nt][3] - m1);
            s0 += S[nt][0] + S[nt][1];
            s1 += S[nt][2] + S[nt][3];
        }
        s0 += __shfl_xor_sync(0xffffffffu, s0, 1);
        s0 += __shfl_xor_sync(0xffffffffu, s0, 2);
        s1 += __shfl_xor_sync(0xffffffffu, s1, 1);
        s1 += __shfl_xor_sync(0xffffffffu, s1, 2);
        l0s = l0s * sc0 + s0;
        l1s = l1s * sc1 + s1;

#pragma unroll
        for (int d = 0; d < 8; d++) {
            Oacc[d][0] *= sc0; Oacc[d][1] *= sc0;
            Oacc[d][2] *= sc1; Oacc[d][3] *= sc1;
        }

        // ---- P @ V (P single fp16) ----
#pragma unroll
        for (int ks = 0; ks < 4; ks++) {
            uint32_t ph[4];
            ph[0] = pack2h(S[2*ks][0],   S[2*ks][1]);
            ph[1] = pack2h(S[2*ks][2],   S[2*ks][3]);
            ph[2] = pack2h(S[2*ks+1][0], S[2*ks+1][1]);
            ph[3] = pack2h(S[2*ks+1][2], S[2*ks+1][3]);

            const uint32_t vrow = vb + (uint32_t)(ks * 16) * 128 + roff_v;
            uint32_t vh[16], vl[16];
#pragma unroll
            for (int dg = 0; dg < 4; dg++) {
                uint32_t dslot = (uint32_t)(((2 * dg + (l >> 4)) ^ l7) << 4);
                ldsm_x4_t(vh[dg*4], vh[dg*4+1], vh[dg*4+2], vh[dg*4+3], vrow + dslot);
            }
#pragma unroll
            for (int dg = 0; dg < 4; dg++) {
                uint32_t dslot = (uint32_t)(((2 * dg + (l >> 4)) ^ l7) << 4);
                ldsm_x4_t(vl[dg*4], vl[dg*4+1], vl[dg*4+2], vl[dg*4+3], vrow + 8192 + dslot);
            }
#pragma unroll
            for (int dt = 0; dt < 8; dt++) {
                mma16816(Oacc[dt], ph, &vh[dt * 2]);
                mma16816(Oacc[dt], ph, &vl[dt * 2]);
            }
        }
        __syncthreads();
    }

    const float r0 = 1.f / l0s, r1 = 1.f / l1s;
    const long row0 = baserow + i0;
    const long row1 = row0 + 8;
#pragma unroll
    for (int dt = 0; dt < 8; dt++) {
        const int col = hc + dt * 8 + colq;
        *(uint32_t*)&O[row0 * DD + col] = pack2h(Oacc[dt][0] * r0, Oacc[dt][1] * r0);
        *(uint32_t*)&O[row1 * DD + col] = pack2h(Oacc[dt][2] * r1, Oacc[dt][3] * r1);
    }
}

// ---------------------------------------------------------------------------
extern "C" void kernel_launch(void* const* d_in, const int* in_sizes, int n_in,
                              void* d_out, int out_size)
{
    const float* q  = (const float*)d_in[0];
    const float* k  = (const float*)d_in[1];
    const float* v  = (const float*)d_in[2];
    const float* am = (const float*)d_in[3];
    const float* wq = (const float*)d_in[4];
    const float* bq = (const float*)d_in[5];
    const float* wk = (const float*)d_in[6];
    const float* bk = (const float*)d_in[7];
    const float* wv = (const float*)d_in[8];
    const float* bv = (const float*)d_in[9];
    const float* wo = (const float*)d_in[10];
    const float* bo = (const float*)d_in[11];
    float* out = (float*)d_out;

    __half *gA, *gWh, *gWl, *gQ, *gKh, *gKl, *gVh, *gVl, *gAO;
    cudaGetSymbolAddress((void**)&gA,  g_A);
    cudaGetSymbolAddress((void**)&gWh, g_Wh);
    cudaGetSymbolAddress((void**)&gWl, g_Wl);
    cudaGetSymbolAddress((void**)&gQ,  g_Q);
    cudaGetSymbolAddress((void**)&gKh, g_Kh);
    cudaGetSymbolAddress((void**)&gKl, g_Kl);
    cudaGetSymbolAddress((void**)&gVh, g_Vh);
    cudaGetSymbolAddress((void**)&gVl, g_Vl);
    cudaGetSymbolAddress((void**)&gAO, g_AO);

    const int convBlocks = (MM * DD) / (256 * 4);
    const dim3 tGrid(32, 32), tBlk(32, 8);
    const dim3 gGrid(DD / 128, MM / 128);
    const size_t gsmem = 2 * STG;                     // 48 KB
    cudaFuncSetAttribute(gemm_hmma<0>, cudaFuncAttributeMaxDynamicSharedMemorySize, (int)gsmem);
    cudaFuncSetAttribute(gemm_hmma<1>, cudaFuncAttributeMaxDynamicSharedMemorySize, (int)gsmem);
    cudaFuncSetAttribute(gemm_hmma<2>, cudaFuncAttributeMaxDynamicSharedMemorySize, (int)gsmem);

    // Q projection -> single fp16
    convT_split<<<tGrid, tBlk>>>(wq, gWh, gWl);
    conv_half<<<convBlocks, 256>>>(q, gA);
    gemm_hmma<1><<<gGrid, 256, gsmem>>>(gA, gWh, gWl, bq, nullptr, gQ, nullptr);
    // K projection -> hi/lo
    convT_split<<<tGrid, tBlk>>>(wk, gWh, gWl);
    conv_half<<<convBlocks, 256>>>(k, gA);
    gemm_hmma<2><<<gGrid, 256, gsmem>>>(gA, gWh, gWl, bk, nullptr, gKh, gKl);
    // V projection -> hi/lo
    convT_split<<<tGrid, tBlk>>>(wv, gWh, gWl);
    conv_half<<<convBlocks, 256>>>(v, gA);
    gemm_hmma<2><<<gGrid, 256, gsmem>>>(gA, gWh, gWl, bv, nullptr, gVh, gVl);

    // attention
    const size_t asmem = 8192 + 2 * ASTG;             // 72 KB
    cudaFuncSetAttribute(attn_hmma, cudaFuncAttributeMaxDynamicSharedMemorySize, (int)asmem);
    attn_hmma<<<dim3(32, NH, BB), 128, asmem>>>(gQ, gKh, gKl, gVh, gVl, am, gAO);

    // output projection -> fp32
    convT_split<<<tGrid, tBlk>>>(wo, gWh, gWl);
    gemm_hmma<0><<<gGrid, 256, gsmem>>>(gAO, gWh, gWl, bo, out, nullptr, nullptr);
}

// round 11
// speedup vs baseline: 6.9049x; 1.2038x over previous
#include <cuda_runtime.h>
#include <cuda_fp16.h>
#include <math.h>
#include <cstdint>

#define BB 4
#define SS 2048
#define DD 1024
#define NH 16
#define DKH 64
#define MM (BB*SS)      // 8192 rows
#define WND 256
#define GLB 16

// ---------------- scratch (__device__ globals, allocation-free rule) -------
__device__ __half g_A[MM*DD];                 // activation (single fp16)
__device__ __half g_Wh[DD*DD], g_Wl[DD*DD];   // weight^T hi/lo
__device__ __half g_Q[MM*DD];
__device__ __half g_K[MM*DD];
__device__ __half g_V[MM*DD];
__device__ __half g_AO[MM*DD];

// ---------------- helpers ---------------------------------------------------
__device__ __forceinline__ uint32_t smem_to_u32(const void* p) {
    uint32_t a;
    asm("{ .reg .u64 t; cvta.to.shared.u64 t, %1; cvt.u32.u64 %0, t; }" : "=r"(a) : "l"(p));
    return a;
}
__device__ __forceinline__ void cp16(uint32_t dst, const void* src) {
    asm volatile("cp.async.cg.shared.global [%0], [%1], 16;" :: "r"(dst), "l"(src));
}
__device__ __forceinline__ void ldsm_x4(uint32_t& r0, uint32_t& r1, uint32_t& r2, uint32_t& r3, uint32_t a) {
    asm volatile("ldmatrix.sync.aligned.m8n8.x4.shared.b16 {%0,%1,%2,%3}, [%4];"
        : "=r"(r0), "=r"(r1), "=r"(r2), "=r"(r3) : "r"(a));
}
__device__ __forceinline__ void ldsm_x4_t(uint32_t& r0, uint32_t& r1, uint32_t& r2, uint32_t& r3, uint32_t a) {
    asm volatile("ldmatrix.sync.aligned.m8n8.x4.trans.shared.b16 {%0,%1,%2,%3}, [%4];"
        : "=r"(r0), "=r"(r1), "=r"(r2), "=r"(r3) : "r"(a));
}
__device__ __forceinline__ void mma16816(float* d, const uint32_t* a, const uint32_t* b) {
    asm volatile("mma.sync.aligned.m16n8k16.row.col.f32.f16.f16.f32 "
        "{%0,%1,%2,%3}, {%4,%5,%6,%7}, {%8,%9}, {%0,%1,%2,%3};"
        : "+f"(d[0]), "+f"(d[1]), "+f"(d[2]), "+f"(d[3])
        : "r"(a[0]), "r"(a[1]), "r"(a[2]), "r"(a[3]), "r"(b[0]), "r"(b[1]));
}
__device__ __forceinline__ uint32_t pack2h(float p0, float p1) {
    __half2 h = __floats2half2_rn(p0, p1);
    return *(uint32_t*)&h;
}

// ---------------------------------------------------------------------------
// Conversions
// ---------------------------------------------------------------------------
__global__ void conv_half(const float* __restrict__ X, __half* __restrict__ Y)
{
    int idx = (blockIdx.x * 256 + threadIdx.x) * 4;
    float4 x = *(const float4*)(X + idx);
    uint2 u{pack2h(x.x, x.y), pack2h(x.z, x.w)};
    *(uint2*)(Y + idx) = u;
}

// W[K][N] -> Wt[N][K] fp16 hi/lo
__global__ void convT_split(const float* __restrict__ W,
                            __half* __restrict__ hiT, __half* __restrict__ loT)
{
    __shared__ float t[32][33];
    int bx = blockIdx.x, by = blockIdx.y, tx = threadIdx.x, ty = threadIdx.y;
#pragma unroll
    for (int i = 0; i < 32; i += 8)
        t[ty + i][tx] = W[(by*32 + ty + i) * DD + bx*32 + tx];
    __syncthreads();
#pragma unroll
    for (int i = 0; i < 32; i += 8) {
        float x = t[tx][ty + i];
        __half h = __float2half_rn(x);
        long o = (long)(bx*32 + ty + i) * DD + by*32 + tx;
        hiT[o] = h;
        loT[o] = __float2half_rn(x - __half2float(h));
    }
}

// ---------------------------------------------------------------------------
// HMMA GEMM: C = A @ B^T + bias.  A single fp16.
// BSPL=true : B split hi/lo, 2 MMA passes (exact in B).
// BSPL=false: B single, 1 pass.
// OUT: 0 = fp32 C, 1 = half Ch.
// ---------------------------------------------------------------------------
#define NCHUNK 32

template<int OUT, bool BSPL>
__global__ __launch_bounds__(256, 2)
void gemm_hmma(const __half* __restrict__ A,
               const __half* __restrict__ Bh, const __half* __restrict__ Bl,
               const float* __restrict__ bias, float* __restrict__ C,
               __half* __restrict__ Ch)
{
    constexpr uint32_t STG = BSPL ? 24576 : 16384;   // stage bytes
    extern __shared__ char smem[];
    const uint32_t sb = smem_to_u32(smem);
    const int tid = threadIdx.x, wid = tid >> 5, l = tid & 31;
    const int m0 = blockIdx.y * 128, n0 = blockIdx.x * 128;
    const int wm = wid >> 2, wn = wid & 3;

    const int lr = tid >> 2;
    const int lc = tid & 3;
    const uint32_t doff = (uint32_t)lr * 64 + (uint32_t)((lc ^ (lr & 3)) << 4);
    const __half* pA  = A  + (long)(m0 + lr) * DD + lc * 8;
    const __half* pBh = Bh + (long)(n0 + lr) * DD + lc * 8;
    const __half* pBl = BSPL ? (Bl + (long)(n0 + lr) * DD + lc * 8) : nullptr;
    const long RSK = (long)64 * DD;

    float acc[4][4][4];
#pragma unroll
    for (int i = 0; i < 4; i++)
#pragma unroll
        for (int j = 0; j < 4; j++)
#pragma unroll
            for (int x = 0; x < 4; x++) acc[i][j][x] = 0.f;

    const int am = wm * 64 + (l & 15);
    const int ar3 = am & 3;
    const int ac = l >> 4;
    const int brow = wn * 32 + ((l >> 4) << 3) + (l & 7);
    const int br3 = brow & 3;
    const int bc = (l >> 3) & 1;

    {
        uint32_t st = sb;
        cp16(st + doff,         pA);   cp16(st + doff + 4096,         pA + RSK);
        cp16(st + 8192 + doff,  pBh);  cp16(st + 8192 + doff + 4096,  pBh + RSK);
        if (BSPL) { cp16(st + 16384 + doff, pBl); cp16(st + 16384 + doff + 4096, pBl + RSK); }
        asm volatile("cp.async.commit_group;");
    }

    for (int c = 0; c < NCHUNK; c++) {
        if (c + 1 < NCHUNK) {
            const int ko = (c + 1) * 32;
            uint32_t st = sb + ((c + 1) & 1) * STG;
            cp16(st + doff,         pA + ko);   cp16(st + doff + 4096,         pA + ko + RSK);
            cp16(st + 8192 + doff,  pBh + ko);  cp16(st + 8192 + doff + 4096,  pBh + ko + RSK);
            if (BSPL) { cp16(st + 16384 + doff, pBl + ko); cp16(st + 16384 + doff + 4096, pBl + ko + RSK); }
            asm volatile("cp.async.commit_group;");
            asm volatile("cp.async.wait_group 1;");
        } else {
            asm volatile("cp.async.wait_group 0;");
        }
        __syncthreads();

        const uint32_t base = sb + (c & 1) * STG;
#pragma unroll
        for (int s = 0; s < 2; s++) {
            const uint32_t achk = (uint32_t)((s * 2 + ac) ^ ar3) << 4;
            const uint32_t bchk = (uint32_t)((s * 2 + bc) ^ br3) << 4;
            const uint32_t aaddr = base + (uint32_t)am * 64 + achk;
            const uint32_t baddr = base + 8192 + (uint32_t)brow * 64 + bchk;

            uint32_t ah[4][4], bh[8];
#pragma unroll
            for (int mt = 0; mt < 4; mt++)
                ldsm_x4(ah[mt][0], ah[mt][1], ah[mt][2], ah[mt][3], aaddr + mt * 1024);
            ldsm_x4(bh[0], bh[1], bh[2], bh[3], baddr);
            ldsm_x4(bh[4], bh[5], bh[6], bh[7], baddr + 1024);
#pragma unroll
            for (int mt = 0; mt < 4; mt++)
#pragma unroll
                for (int nt = 0; nt < 4; nt++)
                    mma16816(acc[mt][nt], ah[mt], &bh[nt * 2]);

            if (BSPL) {
                uint32_t bl[8];
                ldsm_x4(bl[0], bl[1], bl[2], bl[3], baddr + 8192);
                ldsm_x4(bl[4], bl[5], bl[6], bl[7], baddr + 8192 + 1024);
#pragma unroll
                for (int mt = 0; mt < 4; mt++)
#pragma unroll
                    for (int nt = 0; nt < 4; nt++)
                        mma16816(acc[mt][nt], ah[mt], &bl[nt * 2]);
            }
        }
        __syncthreads();
    }

    const int erow = l >> 2, ecol = (l & 3) * 2;
#pragma unroll
    for (int mt = 0; mt < 4; mt++) {
        const long rg = m0 + wm * 64 + mt * 16 + erow;
#pragma unroll
        for (int nt = 0; nt < 4; nt++) {
            const int cg = n0 + wn * 32 + nt * 8 + ecol;
            const float b0 = bias[cg], b1 = bias[cg + 1];
            float v0 = acc[mt][nt][0] + b0, v1 = acc[mt][nt][1] + b1;
            float v2 = acc[mt][nt][2] + b0, v3 = acc[mt][nt][3] + b1;
            if (OUT == 0) {
                float2 o0{v0, v1}, o1{v2, v3};
                *(float2*)&C[rg * DD + cg]       = o0;
                *(float2*)&C[(rg + 8) * DD + cg] = o1;
            } else {
                *(uint32_t*)&Ch[rg * DD + cg]       = pack2h(v0, v1);
                *(uint32_t*)&Ch[(rg + 8) * DD + cg] = pack2h(v2, v3);
            }
        }
    }
}

// ---------------------------------------------------------------------------
// HMMA sparse flash attention. 64q per CTA, 4 warps x 16 rows.
// All operands single fp16, 1-pass QK and PV.
// smem: Q 8KB + 2 stages x 16KB (K,V) = 40KB
// ---------------------------------------------------------------------------
#define ASTG 16384

__global__ __launch_bounds__(128)
void attn_hmma(const __half* __restrict__ Q,
               const __half* __restrict__ K, const __half* __restrict__ V,
               const float* __restrict__ amask, __half* __restrict__ O)
{
    extern __shared__ char smem[];
    const uint32_t sb = smem_to_u32(smem);
    const int tid = threadIdx.x, wid = tid >> 5, l = tid & 31;
    const int qt = blockIdx.x, h = blockIdx.y, b = blockIdx.z;
    const int q0 = qt * 64;
    const long baserow = (long)b * SS;
    const int hc = h * DKH;

    int tiles[32], nlist = 0;
    const int jt_lo = max(0, (q0 - WND) >> 6);
    const int jt_hi = min(31, (q0 + 63 + WND) >> 6);
    if (qt == 0) {
        nlist = 32;
#pragma unroll 8
        for (int i = 0; i < 32; i++) tiles[i] = i;
    } else {
        if (jt_lo > 0) tiles[nlist++] = 0;
        for (int jt = jt_lo; jt <= jt_hi; jt++) tiles[nlist++] = jt;
    }

    // ---- async load Q tile (group 0) ----
    {
        const int row = tid >> 1, cb = (tid & 1) * 4;
        const long src = (baserow + q0 + row) * (long)DD + hc + cb * 8;
        const uint32_t d = sb + row * 128;
#pragma unroll
        for (int i = 0; i < 4; i++) {
            uint32_t off = (uint32_t)(((cb + i) ^ (row & 7)) << 4);
            cp16(d + off, Q + src + i * 8);
        }
        asm volatile("cp.async.commit_group;");
    }
    // ---- async load KV tile 0 (group 1) ----
    const int kvrow = tid >> 1, kvcb = (tid & 1) * 4;
    {
        const long src = (baserow + tiles[0] * 64 + kvrow) * (long)DD + hc + kvcb * 8;
        const uint32_t d = sb + 8192 + kvrow * 128;
#pragma unroll
        for (int i = 0; i < 4; i++) {
            uint32_t off = (uint32_t)(((kvcb + i) ^ (kvrow & 7)) << 4);
            cp16(d + off,        K + src + i * 8);
            cp16(d + 8192 + off, V + src + i * 8);
        }
        asm volatile("cp.async.commit_group;");
    }

    asm volatile("cp.async.wait_group 1;");
    __syncthreads();
    uint32_t qf[4][4];
    {
        const uint32_t qaddr = sb + (uint32_t)(wid * 16 + (l & 15)) * 128;
#pragma unroll
        for (int ks = 0; ks < 4; ks++) {
            uint32_t off = (uint32_t)(((2 * ks + (l >> 4)) ^ (l & 7)) << 4);
            ldsm_x4(qf[ks][0], qf[ks][1], qf[ks][2], qf[ks][3], qaddr + off);
        }
    }

    float Oacc[8][4];
#pragma unroll
    for (int d = 0; d < 8; d++)
#pragma unroll
        for (int x = 0; x < 4; x++) Oacc[d][x] = 0.f;
    float m0 = -INFINITY, m1 = -INFINITY, l0s = 0.f, l1s = 0.f;

    const int i0 = q0 + wid * 16 + (l >> 2);
    const int i1 = i0 + 8;
    const int colq = 2 * (l & 3);
    const uint32_t roff_b = (uint32_t)(((l >> 4) << 3) + (l & 7)) * 128;
    const uint32_t roff_v = (uint32_t)((((l >> 3) & 1) << 3) + (l & 7)) * 128;
    const int l7 = l & 7;

    for (int it = 0; it < nlist; it++) {
        if (it + 1 < nlist) {
            const long src = (baserow + tiles[it + 1] * 64 + kvrow) * (long)DD + hc + kvcb * 8;
            const uint32_t d = sb + 8192 + ((it + 1) & 1) * ASTG + kvrow * 128;
#pragma unroll
            for (int i = 0; i < 4; i++) {
                uint32_t off = (uint32_t)(((kvcb + i) ^ (kvrow & 7)) << 4);
                cp16(d + off,        K + src + i * 8);
                cp16(d + 8192 + off, V + src + i * 8);
            }
            asm volatile("cp.async.commit_group;");
            asm volatile("cp.async.wait_group 1;");
        } else {
            asm volatile("cp.async.wait_group 0;");
        }
        __syncthreads();

        const int j0 = tiles[it] * 64;
        const uint32_t kb = sb + 8192 + (it & 1) * ASTG;
        const uint32_t vb = kb + 8192;

        float S[8][4];
#pragma unroll
        for (int nt = 0; nt < 8; nt++)
#pragma unroll
            for (int x = 0; x < 4; x++) S[nt][x] = 0.f;

#pragma unroll
        for (int ks = 0; ks < 4; ks++) {
            const uint32_t cslot = (uint32_t)(((2 * ks + ((l >> 3) & 1)) ^ l7) << 4);
            uint32_t bh[16];
#pragma unroll
            for (int g = 0; g < 4; g++)
                ldsm_x4(bh[g*4], bh[g*4+1], bh[g*4+2], bh[g*4+3],
                        kb + (uint32_t)(g * 16) * 128 + roff_b + cslot);
#pragma unroll
            for (int nt = 0; nt < 8; nt++)
                mma16816(S[nt], qf[ks], &bh[nt * 2]);
        }

        float t0 = -INFINITY, t1 = -INFINITY;
#pragma unroll
        for (int nt = 0; nt < 8; nt++) {
            const int c0 = j0 + nt * 8 + colq;
            const float a0 = __ldg(&amask[b * SS + c0]);
            const float a1 = __ldg(&amask[b * SS + c0 + 1]);
            bool ok00 = (i0 < GLB) || (c0 < GLB)     || (abs(i0 - c0) <= WND);
            bool ok01 = (i0 < GLB) || (c0 + 1 < GLB) || (abs(i0 - c0 - 1) <= WND);
            bool ok10 = (i1 < GLB) || (c0 < GLB)     || (abs(i1 - c0) <= WND);
            bool ok11 = (i1 < GLB) || (c0 + 1 < GLB) || (abs(i1 - c0 - 1) <= WND);
            S[nt][0] = ok00 ? S[nt][0] * 0.125f + a0 : -1e30f;
            S[nt][1] = ok01 ? S[nt][1] * 0.125f + a1 : -1e30f;
            S[nt][2] = ok10 ? S[nt][2] * 0.125f + a0 : -1e30f;
            S[nt][3] = ok11 ? S[nt][3] * 0.125f + a1 : -1e30f;
            t0 = fmaxf(t0, fmaxf(S[nt][0], S[nt][1]));
            t1 = fmaxf(t1, fmaxf(S[nt][2], S[nt][3]));
        }
        t0 = fmaxf(t0, __shfl_xor_sync(0xffffffffu, t0, 1));
        t0 = fmaxf(t0, __shfl_xor_sync(0xffffffffu, t0, 2));
        t1 = fmaxf(t1, __shfl_xor_sync(0xffffffffu, t1, 1));
        t1 = fmaxf(t1, __shfl_xor_sync(0xffffffffu, t1, 2));

        const float m0n = fmaxf(m0, t0), m1n = fmaxf(m1, t1);
        const float sc0 = __expf(m0 - m0n), sc1 = __expf(m1 - m1n);
        m0 = m0n; m1 = m1n;

        float s0 = 0.f, s1 = 0.f;
#pragma unroll
        for (int nt = 0; nt < 8; nt++) {
            S[nt][0] = __expf(S[nt][0] - m0);
            S[nt][1] = __expf(S[nt][1] - m0);
            S[nt][2] = __expf(S[nt][2] - m1);
            S[nt][3] = __expf(S[nt][3] - m1);
            s0 += S[nt][0] + S[nt][1];
            s1 += S[nt][2] + S[nt][3];
        }
        s0 += __shfl_xor_sync(0xffffffffu, s0, 1);
        s0 += __shfl_xor_sync(0xffffffffu, s0, 2);
        s1 += __shfl_xor_sync(0xffffffffu, s1, 1);
        s1 += __shfl_xor_sync(0xffffffffu, s1, 2);
        l0s = l0s * sc0 + s0;
        l1s = l1s * sc1 + s1;

#pragma unroll
        for (int d = 0; d < 8; d++) {
            Oacc[d][0] *= sc0; Oacc[d][1] *= sc0;
            Oacc[d][2] *= sc1; Oacc[d][3] *= sc1;
        }

        // ---- P @ V ----
#pragma unroll
        for (int ks = 0; ks < 4; ks++) {
            uint32_t ph[4];
            ph[0] = pack2h(S[2*ks][0],   S[2*ks][1]);
            ph[1] = pack2h(S[2*ks][2],   S[2*ks][3]);
            ph[2] = pack2h(S[2*ks+1][0], S[2*ks+1][1]);
            ph[3] = pack2h(S[2*ks+1][2], S[2*ks+1][3]);

            const uint32_t vrow = vb + (uint32_t)(ks * 16) * 128 + roff_v;
            uint32_t vh[16];
#pragma unroll
            for (int dg = 0; dg < 4; dg++) {
                uint32_t dslot = (uint32_t)(((2 * dg + (l >> 4)) ^ l7) << 4);
                ldsm_x4_t(vh[dg*4], vh[dg*4+1], vh[dg*4+2], vh[dg*4+3], vrow + dslot);
            }
#pragma unroll
            for (int dt = 0; dt < 8; dt++)
                mma16816(Oacc[dt], ph, &vh[dt * 2]);
        }
        __syncthreads();
    }

    const float r0 = 1.f / l0s, r1 = 1.f / l1s;
    const long row0 = baserow + i0;
    const long row1 = row0 + 8;
#pragma unroll
    for (int dt = 0; dt < 8; dt++) {
        const int col = hc + dt * 8 + colq;
        *(uint32_t*)&O[row0 * DD + col] = pack2h(Oacc[dt][0] * r0, Oacc[dt][1] * r0);
        *(uint32_t*)&O[row1 * DD + col] = pack2h(Oacc[dt][2] * r1, Oacc[dt][3] * r1);
    }
}

// ---------------------------------------------------------------------------
extern "C" void kernel_launch(void* const* d_in, const int* in_sizes, int n_in,
                              void* d_out, int out_size)
{
    const float* q  = (const float*)d_in[0];
    const float* k  = (const float*)d_in[1];
    const float* v  = (const float*)d_in[2];
    const float* am = (const float*)d_in[3];
    const float* wq = (const float*)d_in[4];
    const float* bq = (const float*)d_in[5];
    const float* wk = (const float*)d_in[6];
    const float* bk = (const float*)d_in[7];
    const float* wv = (const float*)d_in[8];
    const float* bv = (const float*)d_in[9];
    const float* wo = (const float*)d_in[10];
    const float* bo = (const float*)d_in[11];
    float* out = (float*)d_out;

    __half *gA, *gWh, *gWl, *gQ, *gK, *gV, *gAO;
    cudaGetSymbolAddress((void**)&gA,  g_A);
    cudaGetSymbolAddress((void**)&gWh, g_Wh);
    cudaGetSymbolAddress((void**)&gWl, g_Wl);
    cudaGetSymbolAddress((void**)&gQ,  g_Q);
    cudaGetSymbolAddress((void**)&gK,  g_K);
    cudaGetSymbolAddress((void**)&gV,  g_V);
    cudaGetSymbolAddress((void**)&gAO, g_AO);

    const int convBlocks = (MM * DD) / (256 * 4);
    const dim3 tGrid(32, 32), tBlk(32, 8);
    const dim3 gGrid(DD / 128, MM / 128);
    const size_t gsmem2 = 2 * 24576;   // 48 KB (B split)
    const size_t gsmem1 = 2 * 16384;   // 32 KB (B single)
    cudaFuncSetAttribute((const void*)gemm_hmma<1, true>,  cudaFuncAttributeMaxDynamicSharedMemorySize, (int)gsmem2);
    cudaFuncSetAttribute((const void*)gemm_hmma<0, false>, cudaFuncAttributeMaxDynamicSharedMemorySize, (int)gsmem1);

    // Q projection (W split, 2-pass) -> single fp16
    convT_split<<<tGrid, tBlk>>>(wq, gWh, gWl);
    conv_half<<<convBlocks, 256>>>(q, gA);
    gemm_hmma<1, true><<<gGrid, 256, gsmem2>>>(gA, gWh, gWl, bq, nullptr, gQ);
    // K projection -> single fp16
    convT_split<<<tGrid, tBlk>>>(wk, gWh, gWl);
    conv_half<<<convBlocks, 256>>>(k, gA);
    gemm_hmma<1, true><<<gGrid, 256, gsmem2>>>(gA, gWh, gWl, bk, nullptr, gK);
    // V projection -> single fp16
    convT_split<<<tGrid, tBlk>>>(wv, gWh, gWl);
    conv_half<<<convBlocks, 256>>>(v, gA);
    gemm_hmma<1, true><<<gGrid, 256, gsmem2>>>(gA, gWh, gWl, bv, nullptr, gV);

    // attention (1-pass fp16 HMMA flash)
    const size_t asmem = 8192 + 2 * ASTG;   // 40 KB
    cudaFuncSetAttribute(attn_hmma, cudaFuncAttributeMaxDynamicSharedMemorySize, (int)asmem);
    attn_hmma<<<dim3(32, NH, BB), 128, asmem>>>(gQ, gK, gV, am, gAO);

    // output projection (W single, 1-pass) -> fp32
    convT_split<<<tGrid, tBlk>>>(wo, gWh, gWl);
    gemm_hmma<0, false><<<gGrid, 256, gsmem1>>>(gAO, gWh, nullptr, bo, out, nullptr);
}

// round 12
// speedup vs baseline: 8.1524x; 1.1807x over previous
#include <cuda_runtime.h>
#include <cuda_fp16.h>
#include <math.h>
#include <cstdint>

#define BB 4
#define SS 2048
#define DD 1024
#define NH 16
#define DKH 64
#define MM (BB*SS)      // 8192 rows
#define WND 256
#define GLB 16

// ---------------- scratch (__device__ globals, allocation-free rule) -------
__device__ __half g_Aq[MM*DD], g_Ak[MM*DD], g_Av[MM*DD];
__device__ __half g_Wq[DD*DD], g_Wk[DD*DD], g_Wv[DD*DD], g_Wo[DD*DD];
__device__ __half g_Q[MM*DD], g_K[MM*DD], g_V[MM*DD], g_AO[MM*DD];

// ---------------- helpers ---------------------------------------------------
__device__ __forceinline__ uint32_t smem_to_u32(const void* p) {
    uint32_t a;
    asm("{ .reg .u64 t; cvta.to.shared.u64 t, %1; cvt.u32.u64 %0, t; }" : "=r"(a) : "l"(p));
    return a;
}
__device__ __forceinline__ void cp16(uint32_t dst, const void* src) {
    asm volatile("cp.async.cg.shared.global [%0], [%1], 16;" :: "r"(dst), "l"(src));
}
__device__ __forceinline__ void ldsm_x4(uint32_t& r0, uint32_t& r1, uint32_t& r2, uint32_t& r3, uint32_t a) {
    asm volatile("ldmatrix.sync.aligned.m8n8.x4.shared.b16 {%0,%1,%2,%3}, [%4];"
        : "=r"(r0), "=r"(r1), "=r"(r2), "=r"(r3) : "r"(a));
}
__device__ __forceinline__ void ldsm_x4_t(uint32_t& r0, uint32_t& r1, uint32_t& r2, uint32_t& r3, uint32_t a) {
    asm volatile("ldmatrix.sync.aligned.m8n8.x4.trans.shared.b16 {%0,%1,%2,%3}, [%4];"
        : "=r"(r0), "=r"(r1), "=r"(r2), "=r"(r3) : "r"(a));
}
__device__ __forceinline__ void mma16816(float* d, const uint32_t* a, const uint32_t* b) {
    asm volatile("mma.sync.aligned.m16n8k16.row.col.f32.f16.f16.f32 "
        "{%0,%1,%2,%3}, {%4,%5,%6,%7}, {%8,%9}, {%0,%1,%2,%3};"
        : "+f"(d[0]), "+f"(d[1]), "+f"(d[2]), "+f"(d[3])
        : "r"(a[0]), "r"(a[1]), "r"(a[2]), "r"(a[3]), "r"(b[0]), "r"(b[1]));
}
__device__ __forceinline__ uint32_t pack2h(float p0, float p1) {
    __half2 h = __floats2half2_rn(p0, p1);
    return *(uint32_t*)&h;
}

// ---------------------------------------------------------------------------
// Conversions (fused launches)
// ---------------------------------------------------------------------------
__global__ void conv_half3(const float* __restrict__ X0, const float* __restrict__ X1,
                           const float* __restrict__ X2,
                           __half* __restrict__ Y0, __half* __restrict__ Y1,
                           __half* __restrict__ Y2)
{
    const float* X = (blockIdx.y == 0) ? X0 : (blockIdx.y == 1) ? X1 : X2;
    __half*       Y = (blockIdx.y == 0) ? Y0 : (blockIdx.y == 1) ? Y1 : Y2;
    int idx = (blockIdx.x * 256 + threadIdx.x) * 4;
    float4 x = *(const float4*)(X + idx);
    uint2 u{pack2h(x.x, x.y), pack2h(x.z, x.w)};
    *(uint2*)(Y + idx) = u;
}

// W[K][N] -> Wt[N][K] fp16 (4 weights in one launch via blockIdx.z)
__global__ void convT4(const float* __restrict__ W0, const float* __restrict__ W1,
                       const float* __restrict__ W2, const float* __restrict__ W3,
                       __half* __restrict__ O0, __half* __restrict__ O1,
                       __half* __restrict__ O2, __half* __restrict__ O3)
{
    const float* W = (blockIdx.z == 0) ? W0 : (blockIdx.z == 1) ? W1 :
                     (blockIdx.z == 2) ? W2 : W3;
    __half*      O = (blockIdx.z == 0) ? O0 : (blockIdx.z == 1) ? O1 :
                     (blockIdx.z == 2) ? O2 : O3;
    __shared__ float t[32][33];
    int bx = blockIdx.x, by = blockIdx.y, tx = threadIdx.x, ty = threadIdx.y;
#pragma unroll
    for (int i = 0; i < 32; i += 8)
        t[ty + i][tx] = W[(by*32 + ty + i) * DD + bx*32 + tx];
    __syncthreads();
#pragma unroll
    for (int i = 0; i < 32; i += 8)
        O[(long)(bx*32 + ty + i) * DD + by*32 + tx] = __float2half_rn(t[tx][ty + i]);
}

// ---------------------------------------------------------------------------
// HMMA GEMM (1-pass fp16): C = A @ B^T + bias.
// OUT: 0 = fp32 C, 1 = half Ch.  Stage: A 8KB @0, B 8KB @8192, 2 stages.
// ---------------------------------------------------------------------------
#define NCHUNK 32
#define STG 16384

template<int OUT>
__global__ __launch_bounds__(256, 2)
void gemm_hmma(const __half* __restrict__ A, const __half* __restrict__ B,
               const float* __restrict__ bias, float* __restrict__ C,
               __half* __restrict__ Ch)
{
    extern __shared__ char smem[];
    const uint32_t sb = smem_to_u32(smem);
    const int tid = threadIdx.x, wid = tid >> 5, l = tid & 31;
    const int m0 = blockIdx.y * 128, n0 = blockIdx.x * 128;
    const int wm = wid >> 2, wn = wid & 3;

    const int lr = tid >> 2;
    const int lc = tid & 3;
    const uint32_t doff = (uint32_t)lr * 64 + (uint32_t)((lc ^ (lr & 3)) << 4);
    const __half* pA = A + (long)(m0 + lr) * DD + lc * 8;
    const __half* pB = B + (long)(n0 + lr) * DD + lc * 8;
    const long RSK = (long)64 * DD;

    float acc[4][4][4];
#pragma unroll
    for (int i = 0; i < 4; i++)
#pragma unroll
        for (int j = 0; j < 4; j++)
#pragma unroll
            for (int x = 0; x < 4; x++) acc[i][j][x] = 0.f;

    const int am = wm * 64 + (l & 15);
    const int ar3 = am & 3;
    const int ac = l >> 4;
    const int brow = wn * 32 + ((l >> 4) << 3) + (l & 7);
    const int br3 = brow & 3;
    const int bc = (l >> 3) & 1;

    {
        uint32_t st = sb;
        cp16(st + doff,        pA);  cp16(st + doff + 4096,        pA + RSK);
        cp16(st + 8192 + doff, pB);  cp16(st + 8192 + doff + 4096, pB + RSK);
        asm volatile("cp.async.commit_group;");
    }

    for (int c = 0; c < NCHUNK; c++) {
        if (c + 1 < NCHUNK) {
            const int ko = (c + 1) * 32;
            uint32_t st = sb + ((c + 1) & 1) * STG;
            cp16(st + doff,        pA + ko);  cp16(st + doff + 4096,        pA + ko + RSK);
            cp16(st + 8192 + doff, pB + ko);  cp16(st + 8192 + doff + 4096, pB + ko + RSK);
            asm volatile("cp.async.commit_group;");
            asm volatile("cp.async.wait_group 1;");
        } else {
            asm volatile("cp.async.wait_group 0;");
        }
        __syncthreads();

        const uint32_t base = sb + (c & 1) * STG;
#pragma unroll
        for (int s = 0; s < 2; s++) {
            const uint32_t achk = (uint32_t)((s * 2 + ac) ^ ar3) << 4;
            const uint32_t bchk = (uint32_t)((s * 2 + bc) ^ br3) << 4;
            const uint32_t aaddr = base + (uint32_t)am * 64 + achk;
            const uint32_t baddr = base + 8192 + (uint32_t)brow * 64 + bchk;

            uint32_t ah[4][4], bh[8];
#pragma unroll
            for (int mt = 0; mt < 4; mt++)
                ldsm_x4(ah[mt][0], ah[mt][1], ah[mt][2], ah[mt][3], aaddr + mt * 1024);
            ldsm_x4(bh[0], bh[1], bh[2], bh[3], baddr);
            ldsm_x4(bh[4], bh[5], bh[6], bh[7], baddr + 1024);
#pragma unroll
            for (int mt = 0; mt < 4; mt++)
#pragma unroll
                for (int nt = 0; nt < 4; nt++)
                    mma16816(acc[mt][nt], ah[mt], &bh[nt * 2]);
        }
        __syncthreads();
    }

    const int erow = l >> 2, ecol = (l & 3) * 2;
#pragma unroll
    for (int mt = 0; mt < 4; mt++) {
        const long rg = m0 + wm * 64 + mt * 16 + erow;
#pragma unroll
        for (int nt = 0; nt < 4; nt++) {
            const int cg = n0 + wn * 32 + nt * 8 + ecol;
            const float b0 = bias[cg], b1 = bias[cg + 1];
            float v0 = acc[mt][nt][0] + b0, v1 = acc[mt][nt][1] + b1;
            float v2 = acc[mt][nt][2] + b0, v3 = acc[mt][nt][3] + b1;
            if (OUT == 0) {
                float2 o0{v0, v1}, o1{v2, v3};
                *(float2*)&C[rg * DD + cg]       = o0;
                *(float2*)&C[(rg + 8) * DD + cg] = o1;
            } else {
                *(uint32_t*)&Ch[rg * DD + cg]       = pack2h(v0, v1);
                *(uint32_t*)&Ch[(rg + 8) * DD + cg] = pack2h(v2, v3);
            }
        }
    }
}

// ---------------------------------------------------------------------------
// HMMA sparse flash attention (unchanged from R11).
// ---------------------------------------------------------------------------
#define ASTG 16384

__global__ __launch_bounds__(128)
void attn_hmma(const __half* __restrict__ Q,
               const __half* __restrict__ K, const __half* __restrict__ V,
               const float* __restrict__ amask, __half* __restrict__ O)
{
    extern __shared__ char smem[];
    const uint32_t sb = smem_to_u32(smem);
    const int tid = threadIdx.x, wid = tid >> 5, l = tid & 31;
    const int qt = blockIdx.x, h = blockIdx.y, b = blockIdx.z;
    const int q0 = qt * 64;
    const long baserow = (long)b * SS;
    const int hc = h * DKH;

    int tiles[32], nlist = 0;
    const int jt_lo = max(0, (q0 - WND) >> 6);
    const int jt_hi = min(31, (q0 + 63 + WND) >> 6);
    if (qt == 0) {
        nlist = 32;
#pragma unroll 8
        for (int i = 0; i < 32; i++) tiles[i] = i;
    } else {
        if (jt_lo > 0) tiles[nlist++] = 0;
        for (int jt = jt_lo; jt <= jt_hi; jt++) tiles[nlist++] = jt;
    }

    {
        const int row = tid >> 1, cb = (tid & 1) * 4;
        const long src = (baserow + q0 + row) * (long)DD + hc + cb * 8;
        const uint32_t d = sb + row * 128;
#pragma unroll
        for (int i = 0; i < 4; i++) {
            uint32_t off = (uint32_t)(((cb + i) ^ (row & 7)) << 4);
            cp16(d + off, Q + src + i * 8);
        }
        asm volatile("cp.async.commit_group;");
    }
    const int kvrow = tid >> 1, kvcb = (tid & 1) * 4;
    {
        const long src = (baserow + tiles[0] * 64 + kvrow) * (long)DD + hc + kvcb * 8;
        const uint32_t d = sb + 8192 + kvrow * 128;
#pragma unroll
        for (int i = 0; i < 4; i++) {
            uint32_t off = (uint32_t)(((kvcb + i) ^ (kvrow & 7)) << 4);
            cp16(d + off,        K + src + i * 8);
            cp16(d + 8192 + off, V + src + i * 8);
        }
        asm volatile("cp.async.commit_group;");
    }

    asm volatile("cp.async.wait_group 1;");
    __syncthreads();
    uint32_t qf[4][4];
    {
        const uint32_t qaddr = sb + (uint32_t)(wid * 16 + (l & 15)) * 128;
#pragma unroll
        for (int ks = 0; ks < 4; ks++) {
            uint32_t off = (uint32_t)(((2 * ks + (l >> 4)) ^ (l & 7)) << 4);
            ldsm_x4(qf[ks][0], qf[ks][1], qf[ks][2], qf[ks][3], qaddr + off);
        }
    }

    float Oacc[8][4];
#pragma unroll
    for (int d = 0; d < 8; d++)
#pragma unroll
        for (int x = 0; x < 4; x++) Oacc[d][x] = 0.f;
    float m0 = -INFINITY, m1 = -INFINITY, l0s = 0.f, l1s = 0.f;

    const int i0 = q0 + wid * 16 + (l >> 2);
    const int i1 = i0 + 8;
    const int colq = 2 * (l & 3);
    const uint32_t roff_b = (uint32_t)(((l >> 4) << 3) + (l & 7)) * 128;
    const uint32_t roff_v = (uint32_t)((((l >> 3) & 1) << 3) + (l & 7)) * 128;
    const int l7 = l & 7;

    for (int it = 0; it < nlist; it++) {
        if (it + 1 < nlist) {
            const long src = (baserow + tiles[it + 1] * 64 + kvrow) * (long)DD + hc + kvcb * 8;
            const uint32_t d = sb + 8192 + ((it + 1) & 1) * ASTG + kvrow * 128;
#pragma unroll
            for (int i = 0; i < 4; i++) {
                uint32_t off = (uint32_t)(((kvcb + i) ^ (kvrow & 7)) << 4);
                cp16(d + off,        K + src + i * 8);
                cp16(d + 8192 + off, V + src + i * 8);
            }
            asm volatile("cp.async.commit_group;");
            asm volatile("cp.async.wait_group 1;");
        } else {
            asm volatile("cp.async.wait_group 0;");
        }
        __syncthreads();

        const int j0 = tiles[it] * 64;
        const uint32_t kb = sb + 8192 + (it & 1) * ASTG;
        const uint32_t vb = kb + 8192;

        float S[8][4];
#pragma unroll
        for (int nt = 0; nt < 8; nt++)
#pragma unroll
            for (int x = 0; x < 4; x++) S[nt][x] = 0.f;

#pragma unroll
        for (int ks = 0; ks < 4; ks++) {
            const uint32_t cslot = (uint32_t)(((2 * ks + ((l >> 3) & 1)) ^ l7) << 4);
            uint32_t bh[16];
#pragma unroll
            for (int g = 0; g < 4; g++)
                ldsm_x4(bh[g*4], bh[g*4+1], bh[g*4+2], bh[g*4+3],
                        kb + (uint32_t)(g * 16) * 128 + roff_b + cslot);
#pragma unroll
            for (int nt = 0; nt < 8; nt++)
                mma16816(S[nt], qf[ks], &bh[nt * 2]);
        }

        float t0 = -INFINITY, t1 = -INFINITY;
#pragma unroll
        for (int nt = 0; nt < 8; nt++) {
            const int c0 = j0 + nt * 8 + colq;
            const float a0 = __ldg(&amask[b * SS + c0]);
            const float a1 = __ldg(&amask[b * SS + c0 + 1]);
            bool ok00 = (i0 < GLB) || (c0 < GLB)     || (abs(i0 - c0) <= WND);
            bool ok01 = (i0 < GLB) || (c0 + 1 < GLB) || (abs(i0 - c0 - 1) <= WND);
            bool ok10 = (i1 < GLB) || (c0 < GLB)     || (abs(i1 - c0) <= WND);
            bool ok11 = (i1 < GLB) || (c0 + 1 < GLB) || (abs(i1 - c0 - 1) <= WND);
            S[nt][0] = ok00 ? S[nt][0] * 0.125f + a0 : -1e30f;
            S[nt][1] = ok01 ? S[nt][1] * 0.125f + a1 : -1e30f;
            S[nt][2] = ok10 ? S[nt][2] * 0.125f + a0 : -1e30f;
            S[nt][3] = ok11 ? S[nt][3] * 0.125f + a1 : -1e30f;
            t0 = fmaxf(t0, fmaxf(S[nt][0], S[nt][1]));
            t1 = fmaxf(t1, fmaxf(S[nt][2], S[nt][3]));
        }
        t0 = fmaxf(t0, __shfl_xor_sync(0xffffffffu, t0, 1));
        t0 = fmaxf(t0, __shfl_xor_sync(0xffffffffu, t0, 2));
        t1 = fmaxf(t1, __shfl_xor_sync(0xffffffffu, t1, 1));
        t1 = fmaxf(t1, __shfl_xor_sync(0xffffffffu, t1, 2));

        const float m0n = fmaxf(m0, t0), m1n = fmaxf(m1, t1);
        const float sc0 = __expf(m0 - m0n), sc1 = __expf(m1 - m1n);
        m0 = m0n; m1 = m1n;

        float s0 = 0.f, s1 = 0.f;
#pragma unroll
        for (int nt = 0; nt < 8; nt++) {
            S[nt][0] = __expf(S[nt][0] - m0);
            S[nt][1] = __expf(S[nt][1] - m0);
            S[nt][2] = __expf(S[nt][2] - m1);
            S[nt][3] = __expf(S[nt][3] - m1);
            s0 += S[nt][0] + S[nt][1];
            s1 += S[nt][2] + S[nt][3];
        }
        s0 += __shfl_xor_sync(0xffffffffu, s0, 1);
        s0 += __shfl_xor_sync(0xffffffffu, s0, 2);
        s1 += __shfl_xor_sync(0xffffffffu, s1, 1);
        s1 += __shfl_xor_sync(0xffffffffu, s1, 2);
        l0s = l0s * sc0 + s0;
        l1s = l1s * sc1 + s1;

#pragma unroll
        for (int d = 0; d < 8; d++) {
            Oacc[d][0] *= sc0; Oacc[d][1] *= sc0;
            Oacc[d][2] *= sc1; Oacc[d][3] *= sc1;
        }

#pragma unroll
        for (int ks = 0; ks < 4; ks++) {
            uint32_t ph[4];
            ph[0] = pack2h(S[2*ks][0],   S[2*ks][1]);
            ph[1] = pack2h(S[2*ks][2],   S[2*ks][3]);
            ph[2] = pack2h(S[2*ks+1][0], S[2*ks+1][1]);
            ph[3] = pack2h(S[2*ks+1][2], S[2*ks+1][3]);

            const uint32_t vrow = vb + (uint32_t)(ks * 16) * 128 + roff_v;
            uint32_t vh[16];
#pragma unroll
            for (int dg = 0; dg < 4; dg++) {
                uint32_t dslot = (uint32_t)(((2 * dg + (l >> 4)) ^ l7) << 4);
                ldsm_x4_t(vh[dg*4], vh[dg*4+1], vh[dg*4+2], vh[dg*4+3], vrow + dslot);
            }
#pragma unroll
            for (int dt = 0; dt < 8; dt++)
                mma16816(Oacc[dt], ph, &vh[dt * 2]);
        }
        __syncthreads();
    }

    const float r0 = 1.f / l0s, r1 = 1.f / l1s;
    const long row0 = baserow + i0;
    const long row1 = row0 + 8;
#pragma unroll
    for (int dt = 0; dt < 8; dt++) {
        const int col = hc + dt * 8 + colq;
        *(uint32_t*)&O[row0 * DD + col] = pack2h(Oacc[dt][0] * r0, Oacc[dt][1] * r0);
        *(uint32_t*)&O[row1 * DD + col] = pack2h(Oacc[dt][2] * r1, Oacc[dt][3] * r1);
    }
}

// ---------------------------------------------------------------------------
extern "C" void kernel_launch(void* const* d_in, const int* in_sizes, int n_in,
                              void* d_out, int out_size)
{
    const float* q  = (const float*)d_in[0];
    const float* k  = (const float*)d_in[1];
    const float* v  = (const float*)d_in[2];
    const float* am = (const float*)d_in[3];
    const float* wq = (const float*)d_in[4];
    const float* bq = (const float*)d_in[5];
    const float* wk = (const float*)d_in[6];
    const float* bk = (const float*)d_in[7];
    const float* wv = (const float*)d_in[8];
    const float* bv = (const float*)d_in[9];
    const float* wo = (const float*)d_in[10];
    const float* bo = (const float*)d_in[11];
    float* out = (float*)d_out;

    __half *gAq, *gAk, *gAv, *gWq, *gWk, *gWv, *gWo, *gQ, *gK, *gV, *gAO;
    cudaGetSymbolAddress((void**)&gAq, g_Aq);
    cudaGetSymbolAddress((void**)&gAk, g_Ak);
    cudaGetSymbolAddress((void**)&gAv, g_Av);
    cudaGetSymbolAddress((void**)&gWq, g_Wq);
    cudaGetSymbolAddress((void**)&gWk, g_Wk);
    cudaGetSymbolAddress((void**)&gWv, g_Wv);
    cudaGetSymbolAddress((void**)&gWo, g_Wo);
    cudaGetSymbolAddress((void**)&gQ,  g_Q);
    cudaGetSymbolAddress((void**)&gK,  g_K);
    cudaGetSymbolAddress((void**)&gV,  g_V);
    cudaGetSymbolAddress((void**)&gAO, g_AO);

    const int convBlocks = (MM * DD) / (256 * 4);
    const dim3 gGrid(DD / 128, MM / 128);
    const size_t gsmem = 2 * STG;    // 32 KB
    cudaFuncSetAttribute((const void*)gemm_hmma<0>, cudaFuncAttributeMaxDynamicSharedMemorySize, (int)gsmem);
    cudaFuncSetAttribute((const void*)gemm_hmma<1>, cudaFuncAttributeMaxDynamicSharedMemorySize, (int)gsmem);

    // all weight transposes + all activation conversions (fused launches)
    convT4<<<dim3(32, 32, 4), dim3(32, 8)>>>(wq, wk, wv, wo, gWq, gWk, gWv, gWo);
    conv_half3<<<dim3(convBlocks, 3), 256>>>(q, k, v, gAq, gAk, gAv);

    // projections (1-pass fp16)
    gemm_hmma<1><<<gGrid, 256, gsmem>>>(gAq, gWq, bq, nullptr, gQ);
    gemm_hmma<1><<<gGrid, 256, gsmem>>>(gAk, gWk, bk, nullptr, gK);
    gemm_hmma<1><<<gGrid, 256, gsmem>>>(gAv, gWv, bv, nullptr, gV);

    // attention
    const size_t asmem = 8192 + 2 * ASTG;   // 40 KB
    cudaFuncSetAttribute(attn_hmma, cudaFuncAttributeMaxDynamicSharedMemorySize, (int)asmem);
    attn_hmma<<<dim3(32, NH, BB), 128, asmem>>>(gQ, gK, gV, am, gAO);

    // output projection (1-pass) -> fp32
    gemm_hmma<0><<<gGrid, 256, gsmem>>>(gAO, gWo, bo, out, nullptr);
}

// round 14
// speedup vs baseline: 9.5843x; 1.1756x over previous
#include <cuda_runtime.h>
#include <cuda_fp16.h>
#include <math.h>
#include <cstdint>

#define BB 4
#define SS 2048
#define DD 1024
#define NH 16
#define DKH 64
#define MM (BB*SS)      // 8192 rows
#define WND 256
#define GLB 16

// ---------------- scratch (__device__ globals, allocation-free rule) -------
__device__ __half g_Aq[MM*DD], g_Ak[MM*DD], g_Av[MM*DD];
__device__ __half g_Wq[DD*DD], g_Wk[DD*DD], g_Wv[DD*DD], g_Wo[DD*DD];
__device__ __half g_Q[MM*DD], g_K[MM*DD], g_V[MM*DD], g_AO[MM*DD];

// ---------------- helpers ---------------------------------------------------
__device__ __forceinline__ uint32_t smem_to_u32(const void* p) {
    uint32_t a;
    asm("{ .reg .u64 t; cvta.to.shared.u64 t, %1; cvt.u32.u64 %0, t; }" : "=r"(a) : "l"(p));
    return a;
}
__device__ __forceinline__ void cp16(uint32_t dst, const void* src) {
    asm volatile("cp.async.cg.shared.global [%0], [%1], 16;" :: "r"(dst), "l"(src));
}
__device__ __forceinline__ void ldsm_x4(uint32_t& r0, uint32_t& r1, uint32_t& r2, uint32_t& r3, uint32_t a) {
    asm volatile("ldmatrix.sync.aligned.m8n8.x4.shared.b16 {%0,%1,%2,%3}, [%4];"
        : "=r"(r0), "=r"(r1), "=r"(r2), "=r"(r3) : "r"(a));
}
__device__ __forceinline__ void ldsm_x4_t(uint32_t& r0, uint32_t& r1, uint32_t& r2, uint32_t& r3, uint32_t a) {
    asm volatile("ldmatrix.sync.aligned.m8n8.x4.trans.shared.b16 {%0,%1,%2,%3}, [%4];"
        : "=r"(r0), "=r"(r1), "=r"(r2), "=r"(r3) : "r"(a));
}
__device__ __forceinline__ void mma16816(float* d, const uint32_t* a, const uint32_t* b) {
    asm volatile("mma.sync.aligned.m16n8k16.row.col.f32.f16.f16.f32 "
        "{%0,%1,%2,%3}, {%4,%5,%6,%7}, {%8,%9}, {%0,%1,%2,%3};"
        : "+f"(d[0]), "+f"(d[1]), "+f"(d[2]), "+f"(d[3])
        : "r"(a[0]), "r"(a[1]), "r"(a[2]), "r"(a[3]), "r"(b[0]), "r"(b[1]));
}
__device__ __forceinline__ uint32_t pack2h(float p0, float p1) {
    __half2 h = __floats2half2_rn(p0, p1);
    return *(uint32_t*)&h;
}

// ---------------------------------------------------------------------------
// Conversions (fused launches)
// ---------------------------------------------------------------------------
__global__ void conv_half3(const float* __restrict__ X0, const float* __restrict__ X1,
                           const float* __restrict__ X2,
                           __half* __restrict__ Y0, __half* __restrict__ Y1,
                           __half* __restrict__ Y2)
{
    const float* X = (blockIdx.y == 0) ? X0 : (blockIdx.y == 1) ? X1 : X2;
    __half*       Y = (blockIdx.y == 0) ? Y0 : (blockIdx.y == 1) ? Y1 : Y2;
    int idx = (blockIdx.x * 256 + threadIdx.x) * 4;
    float4 x = *(const float4*)(X + idx);
    uint2 u{pack2h(x.x, x.y), pack2h(x.z, x.w)};
    *(uint2*)(Y + idx) = u;
}

// W[K][N] -> Wt[N][K] fp16 (4 weights in one launch via blockIdx.z)
__global__ void convT4(const float* __restrict__ W0, const float* __restrict__ W1,
                       const float* __restrict__ W2, const float* __restrict__ W3,
                       __half* __restrict__ O0, __half* __restrict__ O1,
                       __half* __restrict__ O2, __half* __restrict__ O3)
{
    const float* W = (blockIdx.z == 0) ? W0 : (blockIdx.z == 1) ? W1 :
                     (blockIdx.z == 2) ? W2 : W3;
    __half*      O = (blockIdx.z == 0) ? O0 : (blockIdx.z == 1) ? O1 :
                     (blockIdx.z == 2) ? O2 : O3;
    __shared__ float t[32][33];
    int bx = blockIdx.x, by = blockIdx.y, tx = threadIdx.x, ty = threadIdx.y;
#pragma unroll
    for (int i = 0; i < 32; i += 8)
        t[ty + i][tx] = W[(by*32 + ty + i) * DD + bx*32 + tx];
    __syncthreads();
#pragma unroll
    for (int i = 0; i < 32; i += 8)
        O[(long)(bx*32 + ty + i) * DD + by*32 + tx] = __float2half_rn(t[tx][ty + i]);
}

// ---------------------------------------------------------------------------
// HMMA GEMM core: 128x128 CTA tile, 128 threads (4 warps, 2x2), warp = 64x64.
// BK=32, 2-stage cp.async. Stage: A 8KB @0, B 8KB @8192.
// ---------------------------------------------------------------------------
#define NCHUNK 32
#define STG 16384

template<int OUT>
__device__ __forceinline__
void gemm_core(const __half* __restrict__ A, const __half* __restrict__ B,
               const float* __restrict__ bias, float* __restrict__ C,
               __half* __restrict__ Ch, char* smem)
{
    const uint32_t sb = smem_to_u32(smem);
    const int tid = threadIdx.x, wid = tid >> 5, l = tid & 31;
    const int m0 = blockIdx.y * 128, n0 = blockIdx.x * 128;
    const int wm = wid >> 1, wn = wid & 1;

    // loader: 128 threads, 4 rows each per tile (lr, +32, +64, +96)
    const int lr = tid >> 2;            // 0..31
    const int lc = tid & 3;             // 16B chunk
    const uint32_t doff = (uint32_t)lr * 64 + (uint32_t)((lc ^ (lr & 3)) << 4);
    const __half* pA = A + (long)(m0 + lr) * DD + lc * 8;
    const __half* pB = B + (long)(n0 + lr) * DD + lc * 8;
    const long R32 = (long)32 * DD;

    float acc[4][8][4];
#pragma unroll
    for (int i = 0; i < 4; i++)
#pragma unroll
        for (int j = 0; j < 8; j++)
#pragma unroll
            for (int x = 0; x < 4; x++) acc[i][j][x] = 0.f;

    const int am = wm * 64 + (l & 15);
    const int ar3 = am & 3;
    const int ac = l >> 4;
    const int brow = wn * 64 + ((l >> 4) << 3) + (l & 7);
    const int br3 = brow & 3;
    const int bc = (l >> 3) & 1;

    {
        uint32_t st = sb;
#pragma unroll
        for (int r = 0; r < 4; r++) {
            cp16(st + doff + r * 2048,        pA + r * R32);
            cp16(st + 8192 + doff + r * 2048, pB + r * R32);
        }
        asm volatile("cp.async.commit_group;");
    }

    for (int c = 0; c < NCHUNK; c++) {
        if (c + 1 < NCHUNK) {
            const int ko = (c + 1) * 32;
            uint32_t st = sb + ((c + 1) & 1) * STG;
#pragma unroll
            for (int r = 0; r < 4; r++) {
                cp16(st + doff + r * 2048,        pA + ko + r * R32);
                cp16(st + 8192 + doff + r * 2048, pB + ko + r * R32);
            }
            asm volatile("cp.async.commit_group;");
            asm volatile("cp.async.wait_group 1;");
        } else {
            asm volatile("cp.async.wait_group 0;");
        }
        __syncthreads();

        const uint32_t base = sb + (c & 1) * STG;
#pragma unroll
        for (int s = 0; s < 2; s++) {
            const uint32_t achk = (uint32_t)((s * 2 + ac) ^ ar3) << 4;
            const uint32_t bchk = (uint32_t)((s * 2 + bc) ^ br3) << 4;
            const uint32_t aaddr = base + (uint32_t)am * 64 + achk;
            const uint32_t baddr = base + 8192 + (uint32_t)brow * 64 + bchk;

            uint32_t ah[4][4], bh[16];
#pragma unroll
            for (int mt = 0; mt < 4; mt++)
                ldsm_x4(ah[mt][0], ah[mt][1], ah[mt][2], ah[mt][3], aaddr + mt * 1024);
#pragma unroll
            for (int g = 0; g < 4; g++)
                ldsm_x4(bh[g*4], bh[g*4+1], bh[g*4+2], bh[g*4+3], baddr + g * 1024);
#pragma unroll
            for (int mt = 0; mt < 4; mt++)
#pragma unroll
                for (int nt = 0; nt < 8; nt++)
                    mma16816(acc[mt][nt], ah[mt], &bh[nt * 2]);
        }
        __syncthreads();
    }

    const int erow = l >> 2, ecol = (l & 3) * 2;
#pragma unroll
    for (int mt = 0; mt < 4; mt++) {
        const long rg = m0 + wm * 64 + mt * 16 + erow;
#pragma unroll
        for (int nt = 0; nt < 8; nt++) {
            const int cg = n0 + wn * 64 + nt * 8 + ecol;
            const float b0 = bias[cg], b1 = bias[cg + 1];
            float v0 = acc[mt][nt][0] + b0, v1 = acc[mt][nt][1] + b1;
            float v2 = acc[mt][nt][2] + b0, v3 = acc[mt][nt][3] + b1;
            if (OUT == 0) {
                float2 o0{v0, v1}, o1{v2, v3};
                *(float2*)&C[rg * DD + cg]       = o0;
                *(float2*)&C[(rg + 8) * DD + cg] = o1;
            } else {
                *(uint32_t*)&Ch[rg * DD + cg]       = pack2h(v0, v1);
                *(uint32_t*)&Ch[(rg + 8) * DD + cg] = pack2h(v2, v3);
            }
        }
    }
}

// fused QKV: blockIdx.z selects (A, W, bias, C)
__global__ __launch_bounds__(128, 2)
void gemm_qkv(const __half* __restrict__ Aq, const __half* __restrict__ Ak,
              const __half* __restrict__ Av,
              const __half* __restrict__ Wq, const __half* __restrict__ Wk,
              const __half* __restrict__ Wv,
              const float* __restrict__ bq, const float* __restrict__ bk,
              const float* __restrict__ bv,
              __half* __restrict__ Cq, __half* __restrict__ Ck,
              __half* __restrict__ Cv)
{
    extern __shared__ char smem[];
    const int z = blockIdx.z;
    const __half* A = (z == 0) ? Aq : (z == 1) ? Ak : Av;
    const __half* W = (z == 0) ? Wq : (z == 1) ? Wk : Wv;
    const float*  b = (z == 0) ? bq : (z == 1) ? bk : bv;
    __half*       Cc = (z == 0) ? Cq : (z == 1) ? Ck : Cv;
    gemm_core<1>(A, W, b, nullptr, Cc, smem);
}

__global__ __launch_bounds__(128, 2)
void gemm_out(const __half* __restrict__ A, const __half* __restrict__ W,
              const float* __restrict__ bias, float* __restrict__ C)
{
    extern __shared__ char smem[];
    gemm_core<0>(A, W, bias, C, nullptr, smem);
}

// ---------------------------------------------------------------------------
// HMMA sparse flash attention (unchanged from R12).
// ---------------------------------------------------------------------------
#define ASTG 16384

__global__ __launch_bounds__(128)
void attn_hmma(const __half* __restrict__ Q,
               const __half* __restrict__ K, const __half* __restrict__ V,
               const float* __restrict__ amask, __half* __restrict__ O)
{
    extern __shared__ char smem[];
    const uint32_t sb = smem_to_u32(smem);
    const int tid = threadIdx.x, wid = tid >> 5, l = tid & 31;
    const int qt = blockIdx.x, h = blockIdx.y, b = blockIdx.z;
    const int q0 = qt * 64;
    const long baserow = (long)b * SS;
    const int hc = h * DKH;

    int tiles[32], nlist = 0;
    const int jt_lo = max(0, (q0 - WND) >> 6);
    const int jt_hi = min(31, (q0 + 63 + WND) >> 6);
    if (qt == 0) {
        nlist = 32;
#pragma unroll 8
        for (int i = 0; i < 32; i++) tiles[i] = i;
    } else {
        if (jt_lo > 0) tiles[nlist++] = 0;
        for (int jt = jt_lo; jt <= jt_hi; jt++) tiles[nlist++] = jt;
    }

    {
        const int row = tid >> 1, cb = (tid & 1) * 4;
        const long src = (baserow + q0 + row) * (long)DD + hc + cb * 8;
        const uint32_t d = sb + row * 128;
#pragma unroll
        for (int i = 0; i < 4; i++) {
            uint32_t off = (uint32_t)(((cb + i) ^ (row & 7)) << 4);
            cp16(d + off, Q + src + i * 8);
        }
        asm volatile("cp.async.commit_group;");
    }
    const int kvrow = tid >> 1, kvcb = (tid & 1) * 4;
    {
        const long src = (baserow + tiles[0] * 64 + kvrow) * (long)DD + hc + kvcb * 8;
        const uint32_t d = sb + 8192 + kvrow * 128;
#pragma unroll
        for (int i = 0; i < 4; i++) {
            uint32_t off = (uint32_t)(((kvcb + i) ^ (kvrow & 7)) << 4);
            cp16(d + off,        K + src + i * 8);
            cp16(d + 8192 + off, V + src + i * 8);
        }
        asm volatile("cp.async.commit_group;");
    }

    asm volatile("cp.async.wait_group 1;");
    __syncthreads();
    uint32_t qf[4][4];
    {
        const uint32_t qaddr = sb + (uint32_t)(wid * 16 + (l & 15)) * 128;
#pragma unroll
        for (int ks = 0; ks < 4; ks++) {
            uint32_t off = (uint32_t)(((2 * ks + (l >> 4)) ^ (l & 7)) << 4);
            ldsm_x4(qf[ks][0], qf[ks][1], qf[ks][2], qf[ks][3], qaddr + off);
        }
    }

    float Oacc[8][4];
#pragma unroll
    for (int d = 0; d < 8; d++)
#pragma unroll
        for (int x = 0; x < 4; x++) Oacc[d][x] = 0.f;
    float m0 = -INFINITY, m1 = -INFINITY, l0s = 0.f, l1s = 0.f;

    const int i0 = q0 + wid * 16 + (l >> 2);
    const int i1 = i0 + 8;
    const int colq = 2 * (l & 3);
    const uint32_t roff_b = (uint32_t)(((l >> 4) << 3) + (l & 7)) * 128;
    const uint32_t roff_v = (uint32_t)((((l >> 3) & 1) << 3) + (l & 7)) * 128;
    const int l7 = l & 7;

    for (int it = 0; it < nlist; it++) {
        if (it + 1 < nlist) {
            const long src = (baserow + tiles[it + 1] * 64 + kvrow) * (long)DD + hc + kvcb * 8;
            const uint32_t d = sb + 8192 + ((it + 1) & 1) * ASTG + kvrow * 128;
#pragma unroll
            for (int i = 0; i < 4; i++) {
                uint32_t off = (uint32_t)(((kvcb + i) ^ (kvrow & 7)) << 4);
                cp16(d + off,        K + src + i * 8);
                cp16(d + 8192 + off, V + src + i * 8);
            }
            asm volatile("cp.async.commit_group;");
            asm volatile("cp.async.wait_group 1;");
        } else {
            asm volatile("cp.async.wait_group 0;");
        }
        __syncthreads();

        const int j0 = tiles[it] * 64;
        const uint32_t kb = sb + 8192 + (it & 1) * ASTG;
        const uint32_t vb = kb + 8192;

        float S[8][4];
#pragma unroll
        for (int nt = 0; nt < 8; nt++)
#pragma unroll
            for (int x = 0; x < 4; x++) S[nt][x] = 0.f;

#pragma unroll
        for (int ks = 0; ks < 4; ks++) {
            const uint32_t cslot = (uint32_t)(((2 * ks + ((l >> 3) & 1)) ^ l7) << 4);
            uint32_t bh[16];
#pragma unroll
            for (int g = 0; g < 4; g++)
                ldsm_x4(bh[g*4], bh[g*4+1], bh[g*4+2], bh[g*4+3],
                        kb + (uint32_t)(g * 16) * 128 + roff_b + cslot);
#pragma unroll
            for (int nt = 0; nt < 8; nt++)
                mma16816(S[nt], qf[ks], &bh[nt * 2]);
        }

        float t0 = -INFINITY, t1 = -INFINITY;
#pragma unroll
        for (int nt = 0; nt < 8; nt++) {
            const int c0 = j0 + nt * 8 + colq;
            const float a0 = __ldg(&amask[b * SS + c0]);
            const float a1 = __ldg(&amask[b * SS + c0 + 1]);
            bool ok00 = (i0 < GLB) || (c0 < GLB)     || (abs(i0 - c0) <= WND);
            bool ok01 = (i0 < GLB) || (c0 + 1 < GLB) || (abs(i0 - c0 - 1) <= WND);
            bool ok10 = (i1 < GLB) || (c0 < GLB)     || (abs(i1 - c0) <= WND);
            bool ok11 = (i1 < GLB) || (c0 + 1 < GLB) || (abs(i1 - c0 - 1) <= WND);
            S[nt][0] = ok00 ? S[nt][0] * 0.125f + a0 : -1e30f;
            S[nt][1] = ok01 ? S[nt][1] * 0.125f + a1 : -1e30f;
            S[nt][2] = ok10 ? S[nt][2] * 0.125f + a0 : -1e30f;
            S[nt][3] = ok11 ? S[nt][3] * 0.125f + a1 : -1e30f;
            t0 = fmaxf(t0, fmaxf(S[nt][0], S[nt][1]));
            t1 = fmaxf(t1, fmaxf(S[nt][2], S[nt][3]));
        }
        t0 = fmaxf(t0, __shfl_xor_sync(0xffffffffu, t0, 1));
        t0 = fmaxf(t0, __shfl_xor_sync(0xffffffffu, t0, 2));
        t1 = fmaxf(t1, __shfl_xor_sync(0xffffffffu, t1, 1));
        t1 = fmaxf(t1, __shfl_xor_sync(0xffffffffu, t1, 2));

        const float m0n = fmaxf(m0, t0), m1n = fmaxf(m1, t1);
        const float sc0 = __expf(m0 - m0n), sc1 = __expf(m1 - m1n);
        m0 = m0n; m1 = m1n;

        float s0 = 0.f, s1 = 0.f;
#pragma unroll
        for (int nt = 0; nt < 8; nt++) {
            S[nt][0] = __expf(S[nt][0] - m0);
            S[nt][1] = __expf(S[nt][1] - m0);
            S[nt][2] = __expf(S[nt][2] - m1);
            S[nt][3] = __expf(S[nt][3] - m1);
            s0 += S[nt][0] + S[nt][1];
            s1 += S[nt][2] + S[nt][3];
        }
        s0 += __shfl_xor_sync(0xffffffffu, s0, 1);
        s0 += __shfl_xor_sync(0xffffffffu, s0, 2);
        s1 += __shfl_xor_sync(0xffffffffu, s1, 1);
        s1 += __shfl_xor_sync(0xffffffffu, s1, 2);
        l0s = l0s * sc0 + s0;
        l1s = l1s * sc1 + s1;

#pragma unroll
        for (int d = 0; d < 8; d++) {
            Oacc[d][0] *= sc0; Oacc[d][1] *= sc0;
            Oacc[d][2] *= sc1; Oacc[d][3] *= sc1;
        }

#pragma unroll
        for (int ks = 0; ks < 4; ks++) {
            uint32_t ph[4];
            ph[0] = pack2h(S[2*ks][0],   S[2*ks][1]);
            ph[1] = pack2h(S[2*ks][2],   S[2*ks][3]);
            ph[2] = pack2h(S[2*ks+1][0], S[2*ks+1][1]);
            ph[3] = pack2h(S[2*ks+1][2], S[2*ks+1][3]);

            const uint32_t vrow = vb + (uint32_t)(ks * 16) * 128 + roff_v;
            uint32_t vh[16];
#pragma unroll
            for (int dg = 0; dg < 4; dg++) {
                uint32_t dslot = (uint32_t)(((2 * dg + (l >> 4)) ^ l7) << 4);
                ldsm_x4_t(vh[dg*4], vh[dg*4+1], vh[dg*4+2], vh[dg*4+3], vrow + dslot);
            }
#pragma unroll
            for (int dt = 0; dt < 8; dt++)
                mma16816(Oacc[dt], ph, &vh[dt * 2]);
        }
        __syncthreads();
    }

    const float r0 = 1.f / l0s, r1 = 1.f / l1s;
    const long row0 = baserow + i0;
    const long row1 = row0 + 8;
#pragma unroll
    for (int dt = 0; dt < 8; dt++) {
        const int col = hc + dt * 8 + colq;
        *(uint32_t*)&O[row0 * DD + col] = pack2h(Oacc[dt][0] * r0, Oacc[dt][1] * r0);
        *(uint32_t*)&O[row1 * DD + col] = pack2h(Oacc[dt][2] * r1, Oacc[dt][3] * r1);
    }
}

// ---------------------------------------------------------------------------
extern "C" void kernel_launch(void* const* d_in, const int* in_sizes, int n_in,
                              void* d_out, int out_size)
{
    const float* q  = (const float*)d_in[0];
    const float* k  = (const float*)d_in[1];
    const float* v  = (const float*)d_in[2];
    const float* am = (const float*)d_in[3];
    const float* wq = (const float*)d_in[4];
    const float* bq = (const float*)d_in[5];
    const float* wk = (const float*)d_in[6];
    const float* bk = (const float*)d_in[7];
    const float* wv = (const float*)d_in[8];
    const float* bv = (const float*)d_in[9];
    const float* wo = (const float*)d_in[10];
    const float* bo = (const float*)d_in[11];
    float* out = (float*)d_out;

    __half *gAq, *gAk, *gAv, *gWq, *gWk, *gWv, *gWo, *gQ, *gK, *gV, *gAO;
    cudaGetSymbolAddress((void**)&gAq, g_Aq);
    cudaGetSymbolAddress((void**)&gAk, g_Ak);
    cudaGetSymbolAddress((void**)&gAv, g_Av);
    cudaGetSymbolAddress((void**)&gWq, g_Wq);
    cudaGetSymbolAddress((void**)&gWk, g_Wk);
    cudaGetSymbolAddress((void**)&gWv, g_Wv);
    cudaGetSymbolAddress((void**)&gWo, g_Wo);
    cudaGetSymbolAddress((void**)&gQ,  g_Q);
    cudaGetSymbolAddress((void**)&gK,  g_K);
    cudaGetSymbolAddress((void**)&gV,  g_V);
    cudaGetSymbolAddress((void**)&gAO, g_AO);

    const int convBlocks = (MM * DD) / (256 * 4);
    const dim3 gGrid(DD / 128, MM / 128);           // 8 x 64
    const size_t gsmem = 2 * STG;                   // 32 KB
    cudaFuncSetAttribute(gemm_qkv, cudaFuncAttributeMaxDynamicSharedMemorySize, (int)gsmem);
    cudaFuncSetAttribute(gemm_out, cudaFuncAttributeMaxDynamicSharedMemorySize, (int)gsmem);

    convT4<<<dim3(32, 32, 4), dim3(32, 8)>>>(wq, wk, wv, wo, gWq, gWk, gWv, gWo);
    conv_half3<<<dim3(convBlocks, 3), 256>>>(q, k, v, gAq, gAk, gAv);

    // fused QKV projections (1-pass fp16, 64x64 warp tiles)
    gemm_qkv<<<dim3(8, 64, 3), 128, gsmem>>>(gAq, gAk, gAv, gWq, gWk, gWv,
                                             bq, bk, bv, gQ, gK, gV);

    // attention
    const size_t asmem = 8192 + 2 * ASTG;           // 40 KB
    cudaFuncSetAttribute(attn_hmma, cudaFuncAttributeMaxDynamicSharedMemorySize, (int)asmem);
    attn_hmma<<<dim3(32, NH, BB), 128, asmem>>>(gQ, gK, gV, am, gAO);

    // output projection -> fp32
    gemm_out<<<gGrid, 128, gsmem>>>(gAO, gWo, bo, out);
}